// round 7
// baseline (speedup 1.0000x reference)
#include <cuda_runtime.h>
#include <cstdint>

#define S_LEN 512
#define BATCH 8
#define HEADS 8
#define DHEAD 64
#define INDIM 512
#define PH    322                 // 5*D + 2
#define PHP   324
#define PROJ  (HEADS * PH)        // 2576
#define MROWS (S_LEN * BATCH)     // 4096

// ---- scratch (static device memory; no allocation at runtime) ----
__device__ float g_normed[MROWS * INDIM];   // 8 MB
__device__ float g_qkvb[MROWS * PROJ];      // 42 MB
__device__ float g_hs[MROWS * INDIM];       // 8 MB

// fp32 -> tf32 round-to-nearest-even (integer path; no cvt.tf32 dependency)
__device__ __forceinline__ uint32_t f2tf32(float x)
{
    uint32_t u = __float_as_uint(x);
    u = (u + 0xFFFu + ((u >> 13) & 1u)) & 0xFFFFE000u;
    return u;
}

// m16n8k8 tf32 tensor-core MMA (legacy path, valid on plain sm_103 target)
__device__ __forceinline__ void mma_tf32(float* c, const uint32_t* a, const uint32_t* b)
{
    asm volatile(
        "mma.sync.aligned.m16n8k8.row.col.f32.tf32.tf32.f32 "
        "{%0,%1,%2,%3}, {%4,%5,%6,%7}, {%8,%9}, {%0,%1,%2,%3};"
        : "+f"(c[0]), "+f"(c[1]), "+f"(c[2]), "+f"(c[3])
        : "r"(a[0]), "r"(a[1]), "r"(a[2]), "r"(a[3]), "r"(b[0]), "r"(b[1]));
}

// ============================================================
// Kernel 1: LayerNorm (biased var, eps=1e-5)
// ============================================================
__global__ void __launch_bounds__(256) ln_kernel(
    const float* __restrict__ x,
    const float* __restrict__ gamma,
    const float* __restrict__ beta)
{
    int m = blockIdx.x;
    int t = threadIdx.x;
    const float* row = x + (size_t)m * INDIM;
    float v0 = row[t];
    float v1 = row[t + 256];

    float s = v0 + v1;
    #pragma unroll
    for (int o = 16; o; o >>= 1) s += __shfl_xor_sync(0xffffffffu, s, o);

    __shared__ float red[8];
    __shared__ float red2[8];
    int w = t >> 5, lane = t & 31;
    if (lane == 0) red[w] = s;
    __syncthreads();
    float tot = 0.f;
    #pragma unroll
    for (int i = 0; i < 8; i++) tot += red[i];
    float mean = tot * (1.0f / INDIM);

    float d0 = v0 - mean, d1 = v1 - mean;
    float sq = d0 * d0 + d1 * d1;
    #pragma unroll
    for (int o = 16; o; o >>= 1) sq += __shfl_xor_sync(0xffffffffu, sq, o);
    if (lane == 0) red2[w] = sq;
    __syncthreads();
    float vtot = 0.f;
    #pragma unroll
    for (int i = 0; i < 8; i++) vtot += red2[i];
    float inv = rsqrtf(vtot * (1.0f / INDIM) + 1e-5f);

    g_normed[(size_t)m * INDIM + t]       = d0 * inv * gamma[t]       + beta[t];
    g_normed[(size_t)m * INDIM + t + 256] = d1 * inv * gamma[t + 256] + beta[t + 256];
}

// ============================================================
// Kernel 2/5: TF32x3 tensor-core GEMM, C = A * B^T (+resid)
// (unchanged from R6 — 643us total baseline)
// ============================================================
#define TC_BM 128
#define TC_BN 128
#define TC_BK 16

template<bool RESID>
__global__ void __launch_bounds__(256) mma_gemm_nt(
    const float* __restrict__ A,
    const float* __restrict__ Bm,
    float* __restrict__ C,
    const float* __restrict__ resid,
    int Ndim, int Kdim)
{
    __shared__ uint32_t Ah[TC_BM][20], Al[TC_BM][20];
    __shared__ uint32_t Bh[TC_BN][20], Bl[TC_BN][20];

    const int tid    = threadIdx.x;
    const int lane   = tid & 31;
    const int wid    = tid >> 5;
    const int warp_m = wid & 3;
    const int warp_n = wid >> 2;
    const int g      = lane >> 2;
    const int tq     = lane & 3;
    const int mBase  = blockIdx.y * TC_BM;
    const int nBase  = blockIdx.x * TC_BN;

    const int lrow = tid >> 2;
    const int lc4  = (tid & 3) * 4;

    float c[2][8][4];
    #pragma unroll
    for (int am = 0; am < 2; am++)
        #pragma unroll
        for (int an = 0; an < 8; an++)
            #pragma unroll
            for (int q = 0; q < 4; q++) c[am][an][q] = 0.f;

    const int NKB = Kdim / TC_BK;

    float4 ra[2], rb[2];
    #pragma unroll
    for (int it = 0; it < 2; it++) {
        int row = lrow + it * 64;
        ra[it] = *reinterpret_cast<const float4*>(A + (size_t)(mBase + row) * Kdim + lc4);
        int nrow = nBase + row;
        rb[it] = (nrow < Ndim)
            ? *reinterpret_cast<const float4*>(Bm + (size_t)nrow * Kdim + lc4)
            : make_float4(0.f, 0.f, 0.f, 0.f);
    }

    for (int kb = 0; kb < NKB; kb++) {
        __syncthreads();
        #pragma unroll
        for (int it = 0; it < 2; it++) {
            int row = lrow + it * 64;
            float xs[4] = {ra[it].x, ra[it].y, ra[it].z, ra[it].w};
            uint32_t h4[4], l4[4];
            #pragma unroll
            for (int q = 0; q < 4; q++) {
                h4[q] = f2tf32(xs[q]);
                l4[q] = f2tf32(xs[q] - __uint_as_float(h4[q]));
            }
            *reinterpret_cast<uint4*>(&Ah[row][lc4]) = make_uint4(h4[0], h4[1], h4[2], h4[3]);
            *reinterpret_cast<uint4*>(&Al[row][lc4]) = make_uint4(l4[0], l4[1], l4[2], l4[3]);

            float ys[4] = {rb[it].x, rb[it].y, rb[it].z, rb[it].w};
            #pragma unroll
            for (int q = 0; q < 4; q++) {
                h4[q] = f2tf32(ys[q]);
                l4[q] = f2tf32(ys[q] - __uint_as_float(h4[q]));
            }
            *reinterpret_cast<uint4*>(&Bh[row][lc4]) = make_uint4(h4[0], h4[1], h4[2], h4[3]);
            *reinterpret_cast<uint4*>(&Bl[row][lc4]) = make_uint4(l4[0], l4[1], l4[2], l4[3]);
        }
        __syncthreads();

        if (kb + 1 < NKB) {
            int ko = (kb + 1) * TC_BK;
            #pragma unroll
            for (int it = 0; it < 2; it++) {
                int row = lrow + it * 64;
                ra[it] = *reinterpret_cast<const float4*>(
                    A + (size_t)(mBase + row) * Kdim + ko + lc4);
                int nrow = nBase + row;
                rb[it] = (nrow < Ndim)
                    ? *reinterpret_cast<const float4*>(Bm + (size_t)nrow * Kdim + ko + lc4)
                    : make_float4(0.f, 0.f, 0.f, 0.f);
            }
        }

        #pragma unroll
        for (int ks = 0; ks < 2; ks++) {
            const int kc = ks * 8 + tq;
            uint32_t ah[2][4], al[2][4];
            #pragma unroll
            for (int am = 0; am < 2; am++) {
                int r0 = warp_m * 32 + am * 16 + g;
                ah[am][0] = Ah[r0][kc];     ah[am][1] = Ah[r0 + 8][kc];
                ah[am][2] = Ah[r0][kc + 4]; ah[am][3] = Ah[r0 + 8][kc + 4];
                al[am][0] = Al[r0][kc];     al[am][1] = Al[r0 + 8][kc];
                al[am][2] = Al[r0][kc + 4]; al[am][3] = Al[r0 + 8][kc + 4];
            }
            #pragma unroll
            for (int an = 0; an < 8; an++) {
                int n0 = warp_n * 64 + an * 8 + g;
                uint32_t bh[2] = {Bh[n0][kc], Bh[n0][kc + 4]};
                uint32_t bl[2] = {Bl[n0][kc], Bl[n0][kc + 4]};
                #pragma unroll
                for (int am = 0; am < 2; am++) {
                    mma_tf32(c[am][an], ah[am], bh);
                    mma_tf32(c[am][an], al[am], bh);
                    mma_tf32(c[am][an], ah[am], bl);
                }
            }
        }
    }

    #pragma unroll
    for (int am = 0; am < 2; am++) {
        int r0 = mBase + warp_m * 32 + am * 16 + g;
        #pragma unroll
        for (int an = 0; an < 8; an++) {
            int col = nBase + warp_n * 64 + an * 8 + 2 * tq;
            if (col < Ndim) {
                float2 v0 = make_float2(c[am][an][0], c[am][an][1]);
                float2 v1 = make_float2(c[am][an][2], c[am][an][3]);
                if (RESID) {
                    float2 q0 = *reinterpret_cast<const float2*>(
                        resid + (size_t)r0 * Ndim + col);
                    float2 q1 = *reinterpret_cast<const float2*>(
                        resid + (size_t)(r0 + 8) * Ndim + col);
                    v0.x += q0.x; v0.y += q0.y;
                    v1.x += q1.x; v1.y += q1.y;
                }
                *reinterpret_cast<float2*>(C + (size_t)r0 * Ndim + col) = v0;
                *reinterpret_cast<float2*>(C + (size_t)(r0 + 8) * Ndim + col) = v1;
            }
        }
    }
}

// ============================================================
// Kernel 3: per-head activations in place on g_qkvb
// ============================================================
__global__ void __launch_bounds__(256) act_kernel()
{
    int m    = blockIdx.x;
    int wp   = threadIdx.x >> 5;
    int lane = threadIdx.x & 31;
    float* base = g_qkvb + (size_t)m * PROJ + wp * PH;

    const int segs[3] = {0, 64, 192};
    #pragma unroll
    for (int si = 0; si < 3; si++) {
        int seg = segs[si];
        float a  = base[seg + lane];
        float bb = base[seg + 32 + lane];
        float mx = fmaxf(a, bb);
        #pragma unroll
        for (int o = 16; o; o >>= 1) mx = fmaxf(mx, __shfl_xor_sync(0xffffffffu, mx, o));
        float ea = __expf(a - mx);
        float eb = __expf(bb - mx);
        float s2 = ea + eb;
        #pragma unroll
        for (int o = 16; o; o >>= 1) s2 += __shfl_xor_sync(0xffffffffu, s2, o);
        float inv = 1.0f / s2;
        base[seg + lane]      = ea * inv;
        base[seg + 32 + lane] = eb * inv;
    }
    if (lane < 2) {
        float v = base[320 + lane];
        base[320 + lane] = 1.0f / (1.0f + __expf(-v));
    }
}

// ============================================================
// Kernel 4: sequential scan v4 — warp-specialized
// 64 CTAs = (b,h); 256 threads.
// Warps 0-3 (WZ group): own W; compute z_{s+1} = W_{s+1} q_{s+1} one
//   step ahead (input-only recurrence) -> z_sh.
// Warps 4-7 (R group): own R; R update (input-only) + the serial h chain:
//   softmax(h_{s-1}) -> e -> hd = R_s e -> h_s = z_s + hd/sum.
// One __syncthreads per step. Inputs triple-buffered in SMEM.
// Each SMSP carries one WZ warp + one R warp -> HW hides stalls.
// ============================================================
__device__ __forceinline__ float dot32(const float* a, const float* __restrict__ b)
{
    float s0 = 0.f, s1 = 0.f, s2 = 0.f, s3 = 0.f;
    #pragma unroll
    for (int j = 0; j < 32; j += 4) {
        s0 = fmaf(a[j],     b[j],     s0);
        s1 = fmaf(a[j + 1], b[j + 1], s1);
        s2 = fmaf(a[j + 2], b[j + 2], s2);
        s3 = fmaf(a[j + 3], b[j + 3], s3);
    }
    return (s0 + s1) + (s2 + s3);
}

__device__ __forceinline__ void ld32(float* dst, const float* __restrict__ src)
{
    const float4* p = reinterpret_cast<const float4*>(src);
    #pragma unroll
    for (int q = 0; q < 8; q++) {
        float4 v = p[q];
        dst[q * 4 + 0] = v.x; dst[q * 4 + 1] = v.y;
        dst[q * 4 + 2] = v.z; dst[q * 4 + 3] = v.w;
    }
}

__global__ void __launch_bounds__(256) scan_kernel()
{
    const int bh = blockIdx.x;
    const int b = bh >> 3, h = bh & 7;
    const int t    = threadIdx.x;
    const bool isR = t >= 128;
    const int lt   = t & 127;      // tid within group
    const int i    = lt >> 1;      // row 0..63
    const int c    = lt & 1;       // column half
    const int lane = t & 31;
    const int w    = t >> 5;       // warp 0..7
    const int cofs = c * 32;

    __shared__ float buf[3][PHP];
    __shared__ float h_sh[2][64];
    __shared__ float z_sh[2][64];
    __shared__ float e_sh[4][64];  // per R-warp strip

    const float*  srcBase    = g_qkvb + (size_t)b * PROJ + h * PH;
    const size_t  stepStride = (size_t)BATCH * PROJ;

    float S[32];                   // W (WZ group) or R (R group)
    #pragma unroll
    for (int j = 0; j < 32; j++) S[j] = 0.f;

    // ---- prologue: in_0 -> buf[0], in_1 -> buf[1]; prefetch in_2 ----
    buf[0][t] = srcBase[t];
    if (t < PH - 256) buf[0][t + 256] = srcBase[t + 256];
    buf[1][t] = srcBase[stepStride + t];
    if (t < PH - 256) buf[1][t + 256] = srcBase[stepStride + t + 256];
    float p0 = srcBase[2 * stepStride + t];
    float p1 = 0.f;
    if (t < PH - 256) p1 = srcBase[2 * stepStride + t + 256];
    if (t < 64) h_sh[1][t] = 0.f;        // h_{-1} = 0
    __syncthreads();

    // ---- prologue: WZ computes W_0, z_0 from in_0 ----
    if (!isR) {
        const float* in = buf[0];
        float kreg[32];
        ld32(kreg, in + 64 + cofs);
        float vold = dot32(S, kreg);
        vold += __shfl_xor_sync(0xffffffffu, vold, 1);
        float coef = in[320] * (in[128 + i] - vold);
        #pragma unroll
        for (int j = 0; j < 32; j++) S[j] = fmaf(coef, kreg[j], S[j]);
        float qreg[32];
        ld32(qreg, in + cofs);
        float z = dot32(S, qreg);
        z += __shfl_xor_sync(0xffffffffu, z, 1);
        if (c == 0) z_sh[0][i] = z;
    }
    __syncthreads();

    for (int s = 0; s < S_LEN; s++) {
        // commit in_{s+2} (prefetched) into its triple-buffer slot
        if (s + 2 < S_LEN) {
            float* nb = buf[(s + 2) % 3];
            nb[t] = p0;
            if (t < PH - 256) nb[t + 256] = p1;
        }
        // prefetch in_{s+3}
        if (s + 3 < S_LEN) {
            const float* src = srcBase + (size_t)(s + 3) * stepStride;
            p0 = src[t];
            if (t < PH - 256) p1 = src[t + 256];
        }

        if (isR) {
            const float* in = buf[s % 3];
            // R update from in_s (independent of h — issues first)
            float rk[32];
            ld32(rk, in + 192 + cofs);
            float voldR = dot32(S, rk);
            voldR += __shfl_xor_sync(0xffffffffu, voldR, 1);
            float coefR = in[321] * (in[256 + i] - voldR);
            #pragma unroll
            for (int j = 0; j < 32; j++) S[j] = fmaf(coefR, rk[j], S[j]);

            // softmax(h_{s-1}) — redundant per warp
            const float* hb = h_sh[(s + 1) & 1];
            float h0 = hb[lane];
            float h1 = hb[lane + 32];
            float mx = fmaxf(h0, h1);
            #pragma unroll
            for (int o = 16; o; o >>= 1)
                mx = fmaxf(mx, __shfl_xor_sync(0xffffffffu, mx, o));
            float e0 = __expf(h0 - mx);
            float e1 = __expf(h1 - mx);
            e_sh[w - 4][lane]      = e0;
            e_sh[w - 4][lane + 32] = e1;
            float sm = e0 + e1;
            #pragma unroll
            for (int o = 16; o; o >>= 1)
                sm += __shfl_xor_sync(0xffffffffu, sm, o);
            float invTot = __fdividef(1.0f, sm);
            __syncwarp();

            float er[32];
            ld32(er, &e_sh[w - 4][cofs]);
            float hd = dot32(S, er);
            hd += __shfl_xor_sync(0xffffffffu, hd, 1);
            float hn = z_sh[s & 1][i] + hd * invTot;

            if (c == 0) {
                h_sh[s & 1][i] = hn;
                g_hs[(size_t)(s * BATCH + b) * INDIM + h * DHEAD + i] = hn;
            }
        } else if (s + 1 < S_LEN) {
            // WZ: compute W_{s+1}, z_{s+1} from in_{s+1}
            const float* in = buf[(s + 1) % 3];
            float kreg[32];
            ld32(kreg, in + 64 + cofs);
            float vold = dot32(S, kreg);
            vold += __shfl_xor_sync(0xffffffffu, vold, 1);
            float coef = in[320] * (in[128 + i] - vold);
            #pragma unroll
            for (int j = 0; j < 32; j++) S[j] = fmaf(coef, kreg[j], S[j]);
            float qreg[32];
            ld32(qreg, in + cofs);
            float z = dot32(S, qreg);
            z += __shfl_xor_sync(0xffffffffu, z, 1);
            if (c == 0) z_sh[(s + 1) & 1][i] = z;
        }
        __syncthreads();   // the ONE barrier per step
    }
}

// ============================================================
// Launch
// ============================================================
extern "C" void kernel_launch(void* const* d_in, const int* in_sizes, int n_in,
                              void* d_out, int out_size)
{
    const float* x      = (const float*)d_in[0];
    const float* W_slow = (const float*)d_in[1];
    const float* W_out  = (const float*)d_in[2];
    const float* gamma  = (const float*)d_in[3];
    const float* betap  = (const float*)d_in[4];
    float* out = (float*)d_out;

    float *p_normed = nullptr, *p_qkvb = nullptr, *p_hs = nullptr;
    cudaGetSymbolAddress((void**)&p_normed, g_normed);
    cudaGetSymbolAddress((void**)&p_qkvb,   g_qkvb);
    cudaGetSymbolAddress((void**)&p_hs,     g_hs);

    // 1. LayerNorm
    ln_kernel<<<MROWS, 256>>>(x, gamma, betap);

    // 2. qkvb = normed @ W_slow^T   (M=4096, N=2576, K=512) — tf32x3 mma.sync
    {
        dim3 grid((PROJ + TC_BN - 1) / TC_BN, MROWS / TC_BM);   // 21 x 32
        mma_gemm_nt<false><<<grid, 256>>>(p_normed, W_slow, p_qkvb, nullptr,
                                          PROJ, INDIM);
    }

    // 3. softmax / sigmoid activations in place
    act_kernel<<<MROWS, 256>>>();

    // 4. sequential scan -> g_hs (warp-specialized)
    scan_kernel<<<BATCH * HEADS, 256>>>();

    // 5. out = x + hs @ W_out^T     (M=4096, N=512, K=512) — tf32x3 mma.sync
    {
        dim3 grid(INDIM / TC_BN, MROWS / TC_BM);                // 4 x 32
        mma_gemm_nt<true><<<grid, 256>>>(p_hs, W_out, out, x,
                                         INDIM, HEADS * DHEAD);
    }
}

// round 8
// speedup vs baseline: 1.0778x; 1.0778x over previous
#include <cuda_runtime.h>
#include <cstdint>

#define S_LEN 512
#define BATCH 8
#define HEADS 8
#define DHEAD 64
#define INDIM 512
#define PH    322                 // 5*D + 2
#define PHP   324
#define PROJ  (HEADS * PH)        // 2576
#define MROWS (S_LEN * BATCH)     // 4096

typedef unsigned long long ull;

// ---- scratch (static device memory; no allocation at runtime) ----
__device__ float g_normed[MROWS * INDIM];   // 8 MB
__device__ float g_qkvb[MROWS * PROJ];      // 42 MB
__device__ float g_hs[MROWS * INDIM];       // 8 MB

// ---- packed f32x2 helpers (Blackwell FFMA2; plain-sm_103-safe) ----
__device__ __forceinline__ ull fma_f32x2(ull a, ull b, ull c)
{
    ull d;
    asm("fma.rn.f32x2 %0, %1, %2, %3;" : "=l"(d) : "l"(a), "l"(b), "l"(c));
    return d;
}
__device__ __forceinline__ ull add_f32x2(ull a, ull b)
{
    ull d;
    asm("add.rn.f32x2 %0, %1, %2;" : "=l"(d) : "l"(a), "l"(b));
    return d;
}
__device__ __forceinline__ ull pack_dup(float x)
{
    ull d;
    asm("mov.b64 %0, {%1, %1};" : "=l"(d) : "f"(x));
    return d;
}
__device__ __forceinline__ void unpack2(ull v, float& lo, float& hi)
{
    asm("mov.b64 {%0, %1}, %2;" : "=f"(lo), "=f"(hi) : "l"(v));
}

// fp32 -> tf32 RN-even (integer path)
__device__ __forceinline__ uint32_t f2tf32(float x)
{
    uint32_t u = __float_as_uint(x);
    u = (u + 0xFFFu + ((u >> 13) & 1u)) & 0xFFFFE000u;
    return u;
}

// m16n8k8 tf32 tensor-core MMA (legacy path, valid on plain sm_103)
__device__ __forceinline__ void mma_tf32(float* c, const uint32_t* a, const uint32_t* b)
{
    asm volatile(
        "mma.sync.aligned.m16n8k8.row.col.f32.tf32.tf32.f32 "
        "{%0,%1,%2,%3}, {%4,%5,%6,%7}, {%8,%9}, {%0,%1,%2,%3};"
        : "+f"(c[0]), "+f"(c[1]), "+f"(c[2]), "+f"(c[3])
        : "r"(a[0]), "r"(a[1]), "r"(a[2]), "r"(a[3]), "r"(b[0]), "r"(b[1]));
}

// ============================================================
// Kernel 1: LayerNorm (biased var, eps=1e-5)
// ============================================================
__global__ void __launch_bounds__(256) ln_kernel(
    const float* __restrict__ x,
    const float* __restrict__ gamma,
    const float* __restrict__ beta)
{
    int m = blockIdx.x;
    int t = threadIdx.x;
    const float* row = x + (size_t)m * INDIM;
    float v0 = row[t];
    float v1 = row[t + 256];

    float s = v0 + v1;
    #pragma unroll
    for (int o = 16; o; o >>= 1) s += __shfl_xor_sync(0xffffffffu, s, o);

    __shared__ float red[8];
    __shared__ float red2[8];
    int w = t >> 5, lane = t & 31;
    if (lane == 0) red[w] = s;
    __syncthreads();
    float tot = 0.f;
    #pragma unroll
    for (int i = 0; i < 8; i++) tot += red[i];
    float mean = tot * (1.0f / INDIM);

    float d0 = v0 - mean, d1 = v1 - mean;
    float sq = d0 * d0 + d1 * d1;
    #pragma unroll
    for (int o = 16; o; o >>= 1) sq += __shfl_xor_sync(0xffffffffu, sq, o);
    if (lane == 0) red2[w] = sq;
    __syncthreads();
    float vtot = 0.f;
    #pragma unroll
    for (int i = 0; i < 8; i++) vtot += red2[i];
    float inv = rsqrtf(vtot * (1.0f / INDIM) + 1e-5f);

    g_normed[(size_t)m * INDIM + t]       = d0 * inv * gamma[t]       + beta[t];
    g_normed[(size_t)m * INDIM + t + 256] = d1 * inv * gamma[t + 256] + beta[t + 256];
}

// ============================================================
// Kernel 2/5: TF32x3 tensor-core GEMM, C = A * B^T (+resid)
// (unchanged from R6)
// ============================================================
#define TC_BM 128
#define TC_BN 128
#define TC_BK 16

template<bool RESID>
__global__ void __launch_bounds__(256) mma_gemm_nt(
    const float* __restrict__ A,
    const float* __restrict__ Bm,
    float* __restrict__ C,
    const float* __restrict__ resid,
    int Ndim, int Kdim)
{
    __shared__ uint32_t Ah[TC_BM][20], Al[TC_BM][20];
    __shared__ uint32_t Bh[TC_BN][20], Bl[TC_BN][20];

    const int tid    = threadIdx.x;
    const int lane   = tid & 31;
    const int wid    = tid >> 5;
    const int warp_m = wid & 3;
    const int warp_n = wid >> 2;
    const int g      = lane >> 2;
    const int tq     = lane & 3;
    const int mBase  = blockIdx.y * TC_BM;
    const int nBase  = blockIdx.x * TC_BN;

    const int lrow = tid >> 2;
    const int lc4  = (tid & 3) * 4;

    float c[2][8][4];
    #pragma unroll
    for (int am = 0; am < 2; am++)
        #pragma unroll
        for (int an = 0; an < 8; an++)
            #pragma unroll
            for (int q = 0; q < 4; q++) c[am][an][q] = 0.f;

    const int NKB = Kdim / TC_BK;

    float4 ra[2], rb[2];
    #pragma unroll
    for (int it = 0; it < 2; it++) {
        int row = lrow + it * 64;
        ra[it] = *reinterpret_cast<const float4*>(A + (size_t)(mBase + row) * Kdim + lc4);
        int nrow = nBase + row;
        rb[it] = (nrow < Ndim)
            ? *reinterpret_cast<const float4*>(Bm + (size_t)nrow * Kdim + lc4)
            : make_float4(0.f, 0.f, 0.f, 0.f);
    }

    for (int kb = 0; kb < NKB; kb++) {
        __syncthreads();
        #pragma unroll
        for (int it = 0; it < 2; it++) {
            int row = lrow + it * 64;
            float xs[4] = {ra[it].x, ra[it].y, ra[it].z, ra[it].w};
            uint32_t h4[4], l4[4];
            #pragma unroll
            for (int q = 0; q < 4; q++) {
                h4[q] = f2tf32(xs[q]);
                l4[q] = f2tf32(xs[q] - __uint_as_float(h4[q]));
            }
            *reinterpret_cast<uint4*>(&Ah[row][lc4]) = make_uint4(h4[0], h4[1], h4[2], h4[3]);
            *reinterpret_cast<uint4*>(&Al[row][lc4]) = make_uint4(l4[0], l4[1], l4[2], l4[3]);

            float ys[4] = {rb[it].x, rb[it].y, rb[it].z, rb[it].w};
            #pragma unroll
            for (int q = 0; q < 4; q++) {
                h4[q] = f2tf32(ys[q]);
                l4[q] = f2tf32(ys[q] - __uint_as_float(h4[q]));
            }
            *reinterpret_cast<uint4*>(&Bh[row][lc4]) = make_uint4(h4[0], h4[1], h4[2], h4[3]);
            *reinterpret_cast<uint4*>(&Bl[row][lc4]) = make_uint4(l4[0], l4[1], l4[2], l4[3]);
        }
        __syncthreads();

        if (kb + 1 < NKB) {
            int ko = (kb + 1) * TC_BK;
            #pragma unroll
            for (int it = 0; it < 2; it++) {
                int row = lrow + it * 64;
                ra[it] = *reinterpret_cast<const float4*>(
                    A + (size_t)(mBase + row) * Kdim + ko + lc4);
                int nrow = nBase + row;
                rb[it] = (nrow < Ndim)
                    ? *reinterpret_cast<const float4*>(Bm + (size_t)nrow * Kdim + ko + lc4)
                    : make_float4(0.f, 0.f, 0.f, 0.f);
            }
        }

        #pragma unroll
        for (int ks = 0; ks < 2; ks++) {
            const int kc = ks * 8 + tq;
            uint32_t ah[2][4], al[2][4];
            #pragma unroll
            for (int am = 0; am < 2; am++) {
                int r0 = warp_m * 32 + am * 16 + g;
                ah[am][0] = Ah[r0][kc];     ah[am][1] = Ah[r0 + 8][kc];
                ah[am][2] = Ah[r0][kc + 4]; ah[am][3] = Ah[r0 + 8][kc + 4];
                al[am][0] = Al[r0][kc];     al[am][1] = Al[r0 + 8][kc];
                al[am][2] = Al[r0][kc + 4]; al[am][3] = Al[r0 + 8][kc + 4];
            }
            #pragma unroll
            for (int an = 0; an < 8; an++) {
                int n0 = warp_n * 64 + an * 8 + g;
                uint32_t bh[2] = {Bh[n0][kc], Bh[n0][kc + 4]};
                uint32_t bl[2] = {Bl[n0][kc], Bl[n0][kc + 4]};
                #pragma unroll
                for (int am = 0; am < 2; am++) {
                    mma_tf32(c[am][an], ah[am], bh);
                    mma_tf32(c[am][an], al[am], bh);
                    mma_tf32(c[am][an], ah[am], bl);
                }
            }
        }
    }

    #pragma unroll
    for (int am = 0; am < 2; am++) {
        int r0 = mBase + warp_m * 32 + am * 16 + g;
        #pragma unroll
        for (int an = 0; an < 8; an++) {
            int col = nBase + warp_n * 64 + an * 8 + 2 * tq;
            if (col < Ndim) {
                float2 v0 = make_float2(c[am][an][0], c[am][an][1]);
                float2 v1 = make_float2(c[am][an][2], c[am][an][3]);
                if (RESID) {
                    float2 q0 = *reinterpret_cast<const float2*>(
                        resid + (size_t)r0 * Ndim + col);
                    float2 q1 = *reinterpret_cast<const float2*>(
                        resid + (size_t)(r0 + 8) * Ndim + col);
                    v0.x += q0.x; v0.y += q0.y;
                    v1.x += q1.x; v1.y += q1.y;
                }
                *reinterpret_cast<float2*>(C + (size_t)r0 * Ndim + col) = v0;
                *reinterpret_cast<float2*>(C + (size_t)(r0 + 8) * Ndim + col) = v1;
            }
        }
    }
}

// ============================================================
// Kernel 3: per-head activations in place on g_qkvb
// ============================================================
__global__ void __launch_bounds__(256) act_kernel()
{
    int m    = blockIdx.x;
    int wp   = threadIdx.x >> 5;
    int lane = threadIdx.x & 31;
    float* base = g_qkvb + (size_t)m * PROJ + wp * PH;

    const int segs[3] = {0, 64, 192};
    #pragma unroll
    for (int si = 0; si < 3; si++) {
        int seg = segs[si];
        float a  = base[seg + lane];
        float bb = base[seg + 32 + lane];
        float mx = fmaxf(a, bb);
        #pragma unroll
        for (int o = 16; o; o >>= 1) mx = fmaxf(mx, __shfl_xor_sync(0xffffffffu, mx, o));
        float ea = __expf(a - mx);
        float eb = __expf(bb - mx);
        float s2 = ea + eb;
        #pragma unroll
        for (int o = 16; o; o >>= 1) s2 += __shfl_xor_sync(0xffffffffu, s2, o);
        float inv = 1.0f / s2;
        base[seg + lane]      = ea * inv;
        base[seg + 32 + lane] = eb * inv;
    }
    if (lane < 2) {
        float v = base[320 + lane];
        base[320 + lane] = 1.0f / (1.0f + __expf(-v));
    }
}

// ============================================================
// Kernel 4: sequential scan v5
// v3b structure + packed f32x2 math + 2 independent chains per CTA.
// 32 CTAs x 256 threads; warps 0-3 = chain A, warps 4-7 = chain B.
// Chains decoupled via named barriers (bar.sync 1+chain, 128).
// Per thread: half a row of W and R as 16 packed f32x2 regs each.
// ============================================================
__device__ __forceinline__ void ld16p(ull* dst, const float* __restrict__ src)
{
    const ulonglong2* p = reinterpret_cast<const ulonglong2*>(src);
    #pragma unroll
    for (int q = 0; q < 8; q++) {
        ulonglong2 v = p[q];
        dst[q * 2]     = v.x;
        dst[q * 2 + 1] = v.y;
    }
}

__device__ __forceinline__ float dot16p(const ull* a, const ull* b)
{
    ull s0 = 0ull, s1 = 0ull, s2 = 0ull, s3 = 0ull;
    #pragma unroll
    for (int j = 0; j < 16; j += 4) {
        s0 = fma_f32x2(a[j],     b[j],     s0);
        s1 = fma_f32x2(a[j + 1], b[j + 1], s1);
        s2 = fma_f32x2(a[j + 2], b[j + 2], s2);
        s3 = fma_f32x2(a[j + 3], b[j + 3], s3);
    }
    ull t = add_f32x2(add_f32x2(s0, s1), add_f32x2(s2, s3));
    float lo, hi;
    unpack2(t, lo, hi);
    return lo + hi;
}

__global__ void __launch_bounds__(256) scan_kernel()
{
    const int t     = threadIdx.x;
    const int chain = t >> 7;             // 0 or 1
    const int bh    = blockIdx.x * 2 + chain;
    const int b = bh >> 3, h = bh & 7;
    const int lt   = t & 127;
    const int i    = lt >> 1;             // row 0..63
    const int c    = lt & 1;              // column half
    const int lane = t & 31;
    const int w    = t >> 5;              // warp 0..7
    const int cofs = c * 32;
    const int barid = 1 + chain;

    __shared__ float buf[2][2][PHP];      // [chain][parity][..]
    __shared__ float h_sh[2][2][64];      // [chain][parity][..]
    __shared__ float e_sh[8][64];         // per warp

    ull W2[16], R2[16];
    #pragma unroll
    for (int j = 0; j < 16; j++) { W2[j] = 0ull; R2[j] = 0ull; }

    const float* srcBase   = g_qkvb + (size_t)b * PROJ + h * PH;
    const size_t stepStride = (size_t)BATCH * PROJ;

    // preload step 0; prefetch step 1
    buf[chain][0][lt]       = srcBase[lt];
    buf[chain][0][lt + 128] = srcBase[lt + 128];
    if (lt < PH - 256) buf[chain][0][lt + 256] = srcBase[lt + 256];
    float p0, p1, p2 = 0.f;
    p0 = srcBase[stepStride + lt];
    p1 = srcBase[stepStride + lt + 128];
    if (lt < PH - 256) p2 = srcBase[stepStride + lt + 256];
    if (lt < 64) { h_sh[chain][0][lt] = 0.f; h_sh[chain][1][lt] = 0.f; }
    __syncthreads();

    for (int s = 0; s < S_LEN; s++) {
        // early-commit prefetched inputs for step s+1
        {
            float* nb = buf[chain][(s + 1) & 1];
            nb[lt]       = p0;
            nb[lt + 128] = p1;
            if (lt < PH - 256) nb[lt + 256] = p2;
        }
        // issue prefetch for step s+2
        if (s + 2 < S_LEN) {
            const float* src = srcBase + (size_t)(s + 2) * stepStride;
            p0 = src[lt];
            p1 = src[lt + 128];
            if (lt < PH - 256) p2 = src[lt + 256];
        }

        const float* in = buf[chain][s & 1];
        const float* hb = h_sh[chain][s & 1];

        // softmax(h_prev) — redundant per warp
        float h0 = hb[lane];
        float h1 = hb[lane + 32];
        float mx = fmaxf(h0, h1);
        #pragma unroll
        for (int o = 16; o; o >>= 1)
            mx = fmaxf(mx, __shfl_xor_sync(0xffffffffu, mx, o));
        float e0 = __expf(h0 - mx);
        float e1 = __expf(h1 - mx);
        e_sh[w][lane]      = e0;
        e_sh[w][lane + 32] = e1;
        float sm = e0 + e1;
        #pragma unroll
        for (int o = 16; o; o >>= 1)
            sm += __shfl_xor_sync(0xffffffffu, sm, o);
        float invTot = __fdividef(1.0f, sm);
        __syncwarp();

        // delta-rule fast weight W (packed)
        ull k2[16];
        ld16p(k2, in + 64 + cofs);
        float vold = dot16p(W2, k2);
        vold += __shfl_xor_sync(0xffffffffu, vold, 1);
        float coef = in[320] * (in[128 + i] - vold);
        ull cd = pack_dup(coef);
        #pragma unroll
        for (int j = 0; j < 16; j++) W2[j] = fma_f32x2(cd, k2[j], W2[j]);

        ull q2[16];
        ld16p(q2, in + cofs);
        float z = dot16p(W2, q2);
        z += __shfl_xor_sync(0xffffffffu, z, 1);

        // fast RNN R (packed)
        ull rk2[16];
        ld16p(rk2, in + 192 + cofs);
        float voldR = dot16p(R2, rk2);
        voldR += __shfl_xor_sync(0xffffffffu, voldR, 1);
        float coefR = in[321] * (in[256 + i] - voldR);
        ull crd = pack_dup(coefR);
        #pragma unroll
        for (int j = 0; j < 16; j++) R2[j] = fma_f32x2(crd, rk2[j], R2[j]);

        ull er2[16];
        ld16p(er2, &e_sh[w][cofs]);
        float hd = dot16p(R2, er2);
        hd += __shfl_xor_sync(0xffffffffu, hd, 1);
        float hn = z + hd * invTot;

        if (c == 0) {
            h_sh[chain][(s + 1) & 1][i] = hn;
            g_hs[(size_t)(s * BATCH + b) * INDIM + h * DHEAD + i] = hn;
        }
        // per-chain named barrier (128 threads, warp-aligned groups)
        asm volatile("bar.sync %0, 128;" :: "r"(barid) : "memory");
    }
}

// ============================================================
// Launch
// ============================================================
extern "C" void kernel_launch(void* const* d_in, const int* in_sizes, int n_in,
                              void* d_out, int out_size)
{
    const float* x      = (const float*)d_in[0];
    const float* W_slow = (const float*)d_in[1];
    const float* W_out  = (const float*)d_in[2];
    const float* gamma  = (const float*)d_in[3];
    const float* betap  = (const float*)d_in[4];
    float* out = (float*)d_out;

    float *p_normed = nullptr, *p_qkvb = nullptr, *p_hs = nullptr;
    cudaGetSymbolAddress((void**)&p_normed, g_normed);
    cudaGetSymbolAddress((void**)&p_qkvb,   g_qkvb);
    cudaGetSymbolAddress((void**)&p_hs,     g_hs);

    // 1. LayerNorm
    ln_kernel<<<MROWS, 256>>>(x, gamma, betap);

    // 2. qkvb = normed @ W_slow^T   (M=4096, N=2576, K=512) — tf32x3 mma.sync
    {
        dim3 grid((PROJ + TC_BN - 1) / TC_BN, MROWS / TC_BM);   // 21 x 32
        mma_gemm_nt<false><<<grid, 256>>>(p_normed, W_slow, p_qkvb, nullptr,
                                          PROJ, INDIM);
    }

    // 3. softmax / sigmoid activations in place
    act_kernel<<<MROWS, 256>>>();

    // 4. sequential scan -> g_hs (2 chains per CTA, packed math)
    scan_kernel<<<BATCH * HEADS / 2, 256>>>();

    // 5. out = x + hs @ W_out^T     (M=4096, N=512, K=512) — tf32x3 mma.sync
    {
        dim3 grid(INDIM / TC_BN, MROWS / TC_BM);                // 4 x 32
        mma_gemm_nt<true><<<grid, 256>>>(p_hs, W_out, out, x,
                                         INDIM, HEADS * DHEAD);
    }
}

// round 9
// speedup vs baseline: 1.1838x; 1.0984x over previous
#include <cuda_runtime.h>
#include <cstdint>

#define S_LEN 512
#define BATCH 8
#define HEADS 8
#define DHEAD 64
#define INDIM 512
#define PH    322                 // 5*D + 2
#define PHP   324
#define PROJ  (HEADS * PH)        // 2576
#define MROWS (S_LEN * BATCH)     // 4096
#define OUTD  (HEADS * DHEAD)     // 512

// ---- scratch (static device memory; no allocation at runtime) ----
__device__ float    g_qkvb[MROWS * PROJ];        // 42 MB
__device__ uint32_t g_normed_hi[MROWS * INDIM];  // 8 MB
__device__ uint32_t g_normed_lo[MROWS * INDIM];  // 8 MB
__device__ uint32_t g_hs_hi[MROWS * OUTD];       // 8 MB
__device__ uint32_t g_hs_lo[MROWS * OUTD];       // 8 MB
__device__ uint32_t g_wslow_hi[PROJ * INDIM];    // 5.3 MB
__device__ uint32_t g_wslow_lo[PROJ * INDIM];    // 5.3 MB
__device__ uint32_t g_wout_hi[INDIM * OUTD];     // 1 MB
__device__ uint32_t g_wout_lo[INDIM * OUTD];     // 1 MB

// fp32 -> tf32 RN-even (integer path; plain-sm_103-safe)
__device__ __forceinline__ uint32_t f2tf32(float x)
{
    uint32_t u = __float_as_uint(x);
    u = (u + 0xFFFu + ((u >> 13) & 1u)) & 0xFFFFE000u;
    return u;
}
__device__ __forceinline__ void split_tf32(float x, uint32_t& hi, uint32_t& lo)
{
    hi = f2tf32(x);
    lo = f2tf32(x - __uint_as_float(hi));
}

// m16n8k8 tf32 tensor-core MMA (legacy path, valid on plain sm_103)
__device__ __forceinline__ void mma_tf32(float* c, const uint32_t* a, const uint32_t* b)
{
    asm volatile(
        "mma.sync.aligned.m16n8k8.row.col.f32.tf32.tf32.f32 "
        "{%0,%1,%2,%3}, {%4,%5,%6,%7}, {%8,%9}, {%0,%1,%2,%3};"
        : "+f"(c[0]), "+f"(c[1]), "+f"(c[2]), "+f"(c[3])
        : "r"(a[0]), "r"(a[1]), "r"(a[2]), "r"(a[3]), "r"(b[0]), "r"(b[1]));
}

// ============================================================
// Kernel 0: weight split (fp32 -> tf32 hi/lo), once per launch
// ============================================================
__global__ void __launch_bounds__(256) split_kernel(
    const float* __restrict__ src, uint32_t* __restrict__ dst_hi,
    uint32_t* __restrict__ dst_lo, int n)
{
    int idx = (blockIdx.x * 256 + threadIdx.x) * 4;
    if (idx < n) {
        float4 v = *reinterpret_cast<const float4*>(src + idx);
        uint4 h, l;
        split_tf32(v.x, h.x, l.x);
        split_tf32(v.y, h.y, l.y);
        split_tf32(v.z, h.z, l.z);
        split_tf32(v.w, h.w, l.w);
        *reinterpret_cast<uint4*>(dst_hi + idx) = h;
        *reinterpret_cast<uint4*>(dst_lo + idx) = l;
    }
}

// ============================================================
// Kernel 1: LayerNorm (biased var, eps=1e-5) -> tf32 hi/lo
// ============================================================
__global__ void __launch_bounds__(256) ln_kernel(
    const float* __restrict__ x,
    const float* __restrict__ gamma,
    const float* __restrict__ beta)
{
    int m = blockIdx.x;
    int t = threadIdx.x;
    const float* row = x + (size_t)m * INDIM;
    float v0 = row[t];
    float v1 = row[t + 256];

    float s = v0 + v1;
    #pragma unroll
    for (int o = 16; o; o >>= 1) s += __shfl_xor_sync(0xffffffffu, s, o);

    __shared__ float red[8];
    __shared__ float red2[8];
    int w = t >> 5, lane = t & 31;
    if (lane == 0) red[w] = s;
    __syncthreads();
    float tot = 0.f;
    #pragma unroll
    for (int i = 0; i < 8; i++) tot += red[i];
    float mean = tot * (1.0f / INDIM);

    float d0 = v0 - mean, d1 = v1 - mean;
    float sq = d0 * d0 + d1 * d1;
    #pragma unroll
    for (int o = 16; o; o >>= 1) sq += __shfl_xor_sync(0xffffffffu, sq, o);
    if (lane == 0) red2[w] = sq;
    __syncthreads();
    float vtot = 0.f;
    #pragma unroll
    for (int i = 0; i < 8; i++) vtot += red2[i];
    float inv = rsqrtf(vtot * (1.0f / INDIM) + 1e-5f);

    float r0 = d0 * inv * gamma[t]       + beta[t];
    float r1 = d1 * inv * gamma[t + 256] + beta[t + 256];
    uint32_t h0, l0, h1, l1;
    split_tf32(r0, h0, l0);
    split_tf32(r1, h1, l1);
    size_t base = (size_t)m * INDIM;
    g_normed_hi[base + t]       = h0;
    g_normed_lo[base + t]       = l0;
    g_normed_hi[base + t + 256] = h1;
    g_normed_lo[base + t + 256] = l1;
}

// ============================================================
// Kernel 2/5: TF32x3 tensor-core GEMM on pre-split operands
// C = A * B^T (+resid). A,B given as tf32 hi/lo uint32 arrays.
// BM=BN=128, BK=16, 256 threads; zero conversion ALU in hot loop.
// ============================================================
#define TC_BM 128
#define TC_BN 128
#define TC_BK 16

template<bool RESID>
__global__ void __launch_bounds__(256) mma_gemm_nt(
    const uint32_t* __restrict__ Ahg, const uint32_t* __restrict__ Alg,
    const uint32_t* __restrict__ Bhg, const uint32_t* __restrict__ Blg,
    float* __restrict__ C,
    const float* __restrict__ resid,
    int Ndim, int Kdim)
{
    __shared__ uint32_t Ah[TC_BM][20], Al[TC_BM][20];
    __shared__ uint32_t Bh[TC_BN][20], Bl[TC_BN][20];

    const int tid    = threadIdx.x;
    const int lane   = tid & 31;
    const int wid    = tid >> 5;
    const int warp_m = wid & 3;
    const int warp_n = wid >> 2;
    const int g      = lane >> 2;
    const int tq     = lane & 3;
    const int mBase  = blockIdx.y * TC_BM;
    const int nBase  = blockIdx.x * TC_BN;

    const int lrow = tid >> 2;
    const int lc4  = (tid & 3) * 4;

    float c[2][8][4];
    #pragma unroll
    for (int am = 0; am < 2; am++)
        #pragma unroll
        for (int an = 0; an < 8; an++)
            #pragma unroll
            for (int q = 0; q < 4; q++) c[am][an][q] = 0.f;

    const int NKB = Kdim / TC_BK;
    const uint4 Z4 = make_uint4(0u, 0u, 0u, 0u);

    uint4 rah[2], ral[2], rbh[2], rbl[2];
    #pragma unroll
    for (int it = 0; it < 2; it++) {
        int row = lrow + it * 64;
        size_t aoff = (size_t)(mBase + row) * Kdim + lc4;
        rah[it] = *reinterpret_cast<const uint4*>(Ahg + aoff);
        ral[it] = *reinterpret_cast<const uint4*>(Alg + aoff);
        int nrow = nBase + row;
        if (nrow < Ndim) {
            size_t boff = (size_t)nrow * Kdim + lc4;
            rbh[it] = *reinterpret_cast<const uint4*>(Bhg + boff);
            rbl[it] = *reinterpret_cast<const uint4*>(Blg + boff);
        } else { rbh[it] = Z4; rbl[it] = Z4; }
    }

    for (int kb = 0; kb < NKB; kb++) {
        __syncthreads();
        #pragma unroll
        for (int it = 0; it < 2; it++) {
            int row = lrow + it * 64;
            *reinterpret_cast<uint4*>(&Ah[row][lc4]) = rah[it];
            *reinterpret_cast<uint4*>(&Al[row][lc4]) = ral[it];
            *reinterpret_cast<uint4*>(&Bh[row][lc4]) = rbh[it];
            *reinterpret_cast<uint4*>(&Bl[row][lc4]) = rbl[it];
        }
        __syncthreads();

        if (kb + 1 < NKB) {
            int ko = (kb + 1) * TC_BK;
            #pragma unroll
            for (int it = 0; it < 2; it++) {
                int row = lrow + it * 64;
                size_t aoff = (size_t)(mBase + row) * Kdim + ko + lc4;
                rah[it] = *reinterpret_cast<const uint4*>(Ahg + aoff);
                ral[it] = *reinterpret_cast<const uint4*>(Alg + aoff);
                int nrow = nBase + row;
                if (nrow < Ndim) {
                    size_t boff = (size_t)nrow * Kdim + ko + lc4;
                    rbh[it] = *reinterpret_cast<const uint4*>(Bhg + boff);
                    rbl[it] = *reinterpret_cast<const uint4*>(Blg + boff);
                } else { rbh[it] = Z4; rbl[it] = Z4; }
            }
        }

        #pragma unroll
        for (int ks = 0; ks < 2; ks++) {
            const int kc = ks * 8 + tq;
            uint32_t ah[2][4], al[2][4];
            #pragma unroll
            for (int am = 0; am < 2; am++) {
                int r0 = warp_m * 32 + am * 16 + g;
                ah[am][0] = Ah[r0][kc];     ah[am][1] = Ah[r0 + 8][kc];
                ah[am][2] = Ah[r0][kc + 4]; ah[am][3] = Ah[r0 + 8][kc + 4];
                al[am][0] = Al[r0][kc];     al[am][1] = Al[r0 + 8][kc];
                al[am][2] = Al[r0][kc + 4]; al[am][3] = Al[r0 + 8][kc + 4];
            }
            #pragma unroll
            for (int an = 0; an < 8; an++) {
                int n0 = warp_n * 64 + an * 8 + g;
                uint32_t bh[2] = {Bh[n0][kc], Bh[n0][kc + 4]};
                uint32_t bl[2] = {Bl[n0][kc], Bl[n0][kc + 4]};
                #pragma unroll
                for (int am = 0; am < 2; am++) {
                    mma_tf32(c[am][an], ah[am], bh);
                    mma_tf32(c[am][an], al[am], bh);
                    mma_tf32(c[am][an], ah[am], bl);
                }
            }
        }
    }

    #pragma unroll
    for (int am = 0; am < 2; am++) {
        int r0 = mBase + warp_m * 32 + am * 16 + g;
        #pragma unroll
        for (int an = 0; an < 8; an++) {
            int col = nBase + warp_n * 64 + an * 8 + 2 * tq;
            if (col < Ndim) {
                float2 v0 = make_float2(c[am][an][0], c[am][an][1]);
                float2 v1 = make_float2(c[am][an][2], c[am][an][3]);
                if (RESID) {
                    float2 q0 = *reinterpret_cast<const float2*>(
                        resid + (size_t)r0 * Ndim + col);
                    float2 q1 = *reinterpret_cast<const float2*>(
                        resid + (size_t)(r0 + 8) * Ndim + col);
                    v0.x += q0.x; v0.y += q0.y;
                    v1.x += q1.x; v1.y += q1.y;
                }
                *reinterpret_cast<float2*>(C + (size_t)r0 * Ndim + col) = v0;
                *reinterpret_cast<float2*>(C + (size_t)(r0 + 8) * Ndim + col) = v1;
            }
        }
    }
}

// ============================================================
// Kernel 3: per-head activations in place on g_qkvb
// ============================================================
__global__ void __launch_bounds__(256) act_kernel()
{
    int m    = blockIdx.x;
    int wp   = threadIdx.x >> 5;
    int lane = threadIdx.x & 31;
    float* base = g_qkvb + (size_t)m * PROJ + wp * PH;

    const int segs[3] = {0, 64, 192};
    #pragma unroll
    for (int si = 0; si < 3; si++) {
        int seg = segs[si];
        float a  = base[seg + lane];
        float bb = base[seg + 32 + lane];
        float mx = fmaxf(a, bb);
        #pragma unroll
        for (int o = 16; o; o >>= 1) mx = fmaxf(mx, __shfl_xor_sync(0xffffffffu, mx, o));
        float ea = __expf(a - mx);
        float eb = __expf(bb - mx);
        float s2 = ea + eb;
        #pragma unroll
        for (int o = 16; o; o >>= 1) s2 += __shfl_xor_sync(0xffffffffu, s2, o);
        float inv = 1.0f / s2;
        base[seg + lane]      = ea * inv;
        base[seg + 32 + lane] = eb * inv;
    }
    if (lane < 2) {
        float v = base[320 + lane];
        base[320 + lane] = 1.0f / (1.0f + __expf(-v));
    }
}

// ============================================================
// Kernel 4: sequential scan v3b (proven 330us) -> hs hi/lo
// ============================================================
__device__ __forceinline__ float dot32(const float* a, const float* __restrict__ b)
{
    float s0 = 0.f, s1 = 0.f, s2 = 0.f, s3 = 0.f;
    #pragma unroll
    for (int j = 0; j < 32; j += 4) {
        s0 = fmaf(a[j],     b[j],     s0);
        s1 = fmaf(a[j + 1], b[j + 1], s1);
        s2 = fmaf(a[j + 2], b[j + 2], s2);
        s3 = fmaf(a[j + 3], b[j + 3], s3);
    }
    return (s0 + s1) + (s2 + s3);
}

__device__ __forceinline__ void ld32(float* dst, const float* __restrict__ src)
{
    const float4* p = reinterpret_cast<const float4*>(src);
    #pragma unroll
    for (int q = 0; q < 8; q++) {
        float4 v = p[q];
        dst[q * 4 + 0] = v.x; dst[q * 4 + 1] = v.y;
        dst[q * 4 + 2] = v.z; dst[q * 4 + 3] = v.w;
    }
}

__global__ void __launch_bounds__(128) scan_kernel()
{
    int bh = blockIdx.x;
    int b = bh >> 3, h = bh & 7;
    int t    = threadIdx.x;
    int i    = t >> 1;
    int c    = t & 1;
    int lane = t & 31;
    int w    = t >> 5;

    __shared__ float buf[2][PHP];
    __shared__ float h_sh[2][64];
    __shared__ float e_sh[4][64];

    float W[32], R[32];
    #pragma unroll
    for (int j = 0; j < 32; j++) { W[j] = 0.f; R[j] = 0.f; }

    {
        const float* src = g_qkvb + (size_t)b * PROJ + h * PH;
        buf[0][t]       = src[t];
        buf[0][t + 128] = src[t + 128];
        if (t < PH - 256) buf[0][t + 256] = src[t + 256];
    }
    float p0, p1, p2 = 0.f;
    {
        const float* src = g_qkvb + (size_t)(BATCH + b) * PROJ + h * PH;
        p0 = src[t];
        p1 = src[t + 128];
        if (t < PH - 256) p2 = src[t + 256];
    }
    if (t < 64) { h_sh[0][t] = 0.f; h_sh[1][t] = 0.f; }
    __syncthreads();

    const int cofs = c * 32;

    for (int s = 0; s < S_LEN; s++) {
        {
            float* nb = buf[(s + 1) & 1];
            nb[t]       = p0;
            nb[t + 128] = p1;
            if (t < PH - 256) nb[t + 256] = p2;
        }
        if (s + 2 < S_LEN) {
            const float* src = g_qkvb + (size_t)((s + 2) * BATCH + b) * PROJ + h * PH;
            p0 = src[t];
            p1 = src[t + 128];
            if (t < PH - 256) p2 = src[t + 256];
        }

        const float* in = buf[s & 1];
        const float* hb = h_sh[s & 1];

        float h0 = hb[lane];
        float h1 = hb[lane + 32];
        float mx = fmaxf(h0, h1);
        #pragma unroll
        for (int o = 16; o; o >>= 1) mx = fmaxf(mx, __shfl_xor_sync(0xffffffffu, mx, o));
        float e0 = __expf(h0 - mx);
        float e1 = __expf(h1 - mx);
        e_sh[w][lane]      = e0;
        e_sh[w][lane + 32] = e1;
        float sm = e0 + e1;
        #pragma unroll
        for (int o = 16; o; o >>= 1) sm += __shfl_xor_sync(0xffffffffu, sm, o);
        float invTot = __fdividef(1.0f, sm);
        __syncwarp();

        float kreg[32];
        ld32(kreg, in + 64 + cofs);
        float vold = dot32(W, kreg);
        vold += __shfl_xor_sync(0xffffffffu, vold, 1);
        float coef = in[320] * (in[128 + i] - vold);
        #pragma unroll
        for (int j = 0; j < 32; j++) W[j] = fmaf(coef, kreg[j], W[j]);

        float qreg[32];
        ld32(qreg, in + cofs);
        float z = dot32(W, qreg);
        z += __shfl_xor_sync(0xffffffffu, z, 1);

        float rkreg[32];
        ld32(rkreg, in + 192 + cofs);
        float voldR = dot32(R, rkreg);
        voldR += __shfl_xor_sync(0xffffffffu, voldR, 1);
        float coefR = in[321] * (in[256 + i] - voldR);
        #pragma unroll
        for (int j = 0; j < 32; j++) R[j] = fmaf(coefR, rkreg[j], R[j]);

        float ereg[32];
        ld32(ereg, &e_sh[w][cofs]);
        float hd = dot32(R, ereg);
        hd += __shfl_xor_sync(0xffffffffu, hd, 1);
        float hn = z + hd * invTot;

        if (c == 0) {
            h_sh[(s + 1) & 1][i] = hn;
            uint32_t hi, lo;
            split_tf32(hn, hi, lo);
            size_t idx = (size_t)(s * BATCH + b) * OUTD + h * DHEAD + i;
            g_hs_hi[idx] = hi;
            g_hs_lo[idx] = lo;
        }
        __syncthreads();
    }
}

// ============================================================
// Launch
// ============================================================
extern "C" void kernel_launch(void* const* d_in, const int* in_sizes, int n_in,
                              void* d_out, int out_size)
{
    const float* x      = (const float*)d_in[0];
    const float* W_slow = (const float*)d_in[1];
    const float* W_out  = (const float*)d_in[2];
    const float* gamma  = (const float*)d_in[3];
    const float* betap  = (const float*)d_in[4];
    float* out = (float*)d_out;

    float*    p_qkvb = nullptr;
    uint32_t *p_nh = nullptr, *p_nl = nullptr, *p_hh = nullptr, *p_hl = nullptr;
    uint32_t *p_wsh = nullptr, *p_wsl = nullptr, *p_woh = nullptr, *p_wol = nullptr;
    cudaGetSymbolAddress((void**)&p_qkvb, g_qkvb);
    cudaGetSymbolAddress((void**)&p_nh,   g_normed_hi);
    cudaGetSymbolAddress((void**)&p_nl,   g_normed_lo);
    cudaGetSymbolAddress((void**)&p_hh,   g_hs_hi);
    cudaGetSymbolAddress((void**)&p_hl,   g_hs_lo);
    cudaGetSymbolAddress((void**)&p_wsh,  g_wslow_hi);
    cudaGetSymbolAddress((void**)&p_wsl,  g_wslow_lo);
    cudaGetSymbolAddress((void**)&p_woh,  g_wout_hi);
    cudaGetSymbolAddress((void**)&p_wol,  g_wout_lo);

    // 0. split weights to tf32 hi/lo
    {
        int n1 = PROJ * INDIM;
        split_kernel<<<(n1 / 4 + 255) / 256, 256>>>(W_slow, p_wsh, p_wsl, n1);
        int n2 = INDIM * OUTD;
        split_kernel<<<(n2 / 4 + 255) / 256, 256>>>(W_out, p_woh, p_wol, n2);
    }

    // 1. LayerNorm -> tf32 hi/lo
    ln_kernel<<<MROWS, 256>>>(x, gamma, betap);

    // 2. qkvb = normed @ W_slow^T   (M=4096, N=2576, K=512)
    {
        dim3 grid((PROJ + TC_BN - 1) / TC_BN, MROWS / TC_BM);   // 21 x 32
        mma_gemm_nt<false><<<grid, 256>>>(p_nh, p_nl, p_wsh, p_wsl,
                                          p_qkvb, nullptr, PROJ, INDIM);
    }

    // 3. softmax / sigmoid activations in place
    act_kernel<<<MROWS, 256>>>();

    // 4. sequential scan -> hs hi/lo
    scan_kernel<<<BATCH * HEADS, 128>>>();

    // 5. out = x + hs @ W_out^T     (M=4096, N=512, K=512)
    {
        dim3 grid(INDIM / TC_BN, MROWS / TC_BM);                // 4 x 32
        mma_gemm_nt<true><<<grid, 256>>>(p_hh, p_hl, p_woh, p_wol,
                                         out, x, INDIM, OUTD);
    }
}

// round 10
// speedup vs baseline: 1.2855x; 1.0859x over previous
#include <cuda_runtime.h>
#include <cstdint>

#define S_LEN 512
#define BATCH 8
#define HEADS 8
#define DHEAD 64
#define INDIM 512
#define PH    322                 // 5*D + 2
#define PHP   324
#define PROJ  (HEADS * PH)        // 2576
#define MROWS (S_LEN * BATCH)     // 4096
#define OUTD  (HEADS * DHEAD)     // 512

// ---- scratch (static device memory; no allocation at runtime) ----
__device__ float    g_qkvb[MROWS * PROJ];        // 42 MB
__device__ uint32_t g_normed_hi[MROWS * INDIM];
__device__ uint32_t g_normed_lo[MROWS * INDIM];
__device__ uint32_t g_hs_hi[MROWS * OUTD];
__device__ uint32_t g_hs_lo[MROWS * OUTD];
__device__ uint32_t g_wslow_hi[PROJ * INDIM];
__device__ uint32_t g_wslow_lo[PROJ * INDIM];
__device__ uint32_t g_wout_hi[INDIM * OUTD];
__device__ uint32_t g_wout_lo[INDIM * OUTD];

// fp32 -> tf32 RN-even (integer path; plain-sm_103-safe)
__device__ __forceinline__ uint32_t f2tf32(float x)
{
    uint32_t u = __float_as_uint(x);
    u = (u + 0xFFFu + ((u >> 13) & 1u)) & 0xFFFFE000u;
    return u;
}
__device__ __forceinline__ void split_tf32(float x, uint32_t& hi, uint32_t& lo)
{
    hi = f2tf32(x);
    lo = f2tf32(x - __uint_as_float(hi));
}

// m16n8k8 tf32 tensor-core MMA
__device__ __forceinline__ void mma_tf32(float* c, const uint32_t* a, const uint32_t* b)
{
    asm volatile(
        "mma.sync.aligned.m16n8k8.row.col.f32.tf32.tf32.f32 "
        "{%0,%1,%2,%3}, {%4,%5,%6,%7}, {%8,%9}, {%0,%1,%2,%3};"
        : "+f"(c[0]), "+f"(c[1]), "+f"(c[2]), "+f"(c[3])
        : "r"(a[0]), "r"(a[1]), "r"(a[2]), "r"(a[3]), "r"(b[0]), "r"(b[1]));
}

// cp.async helpers (sm_80 baseline feature; OK on plain sm_103 target)
__device__ __forceinline__ uint32_t smem_u32(const void* p)
{
    uint32_t a;
    asm("{ .reg .u64 t; cvta.to.shared.u64 t, %1; cvt.u32.u64 %0, t; }"
        : "=r"(a) : "l"(p));
    return a;
}
__device__ __forceinline__ void cp_async16(uint32_t dst, const void* src, int src_bytes)
{
    asm volatile("cp.async.cg.shared.global [%0], [%1], 16, %2;"
                 :: "r"(dst), "l"(src), "r"(src_bytes) : "memory");
}
#define CP_COMMIT() asm volatile("cp.async.commit_group;" ::: "memory")
template<int N>
__device__ __forceinline__ void cp_wait()
{
    asm volatile("cp.async.wait_group %0;" :: "n"(N) : "memory");
}

// ============================================================
// Kernel 0: weight split (fp32 -> tf32 hi/lo)
// ============================================================
__global__ void __launch_bounds__(256) split_kernel(
    const float* __restrict__ src, uint32_t* __restrict__ dst_hi,
    uint32_t* __restrict__ dst_lo, int n)
{
    int idx = (blockIdx.x * 256 + threadIdx.x) * 4;
    if (idx < n) {
        float4 v = *reinterpret_cast<const float4*>(src + idx);
        uint4 h, l;
        split_tf32(v.x, h.x, l.x);
        split_tf32(v.y, h.y, l.y);
        split_tf32(v.z, h.z, l.z);
        split_tf32(v.w, h.w, l.w);
        *reinterpret_cast<uint4*>(dst_hi + idx) = h;
        *reinterpret_cast<uint4*>(dst_lo + idx) = l;
    }
}

// ============================================================
// Kernel 1: LayerNorm -> tf32 hi/lo
// ============================================================
__global__ void __launch_bounds__(256) ln_kernel(
    const float* __restrict__ x,
    const float* __restrict__ gamma,
    const float* __restrict__ beta)
{
    int m = blockIdx.x;
    int t = threadIdx.x;
    const float* row = x + (size_t)m * INDIM;
    float v0 = row[t];
    float v1 = row[t + 256];

    float s = v0 + v1;
    #pragma unroll
    for (int o = 16; o; o >>= 1) s += __shfl_xor_sync(0xffffffffu, s, o);

    __shared__ float red[8];
    __shared__ float red2[8];
    int w = t >> 5, lane = t & 31;
    if (lane == 0) red[w] = s;
    __syncthreads();
    float tot = 0.f;
    #pragma unroll
    for (int i = 0; i < 8; i++) tot += red[i];
    float mean = tot * (1.0f / INDIM);

    float d0 = v0 - mean, d1 = v1 - mean;
    float sq = d0 * d0 + d1 * d1;
    #pragma unroll
    for (int o = 16; o; o >>= 1) sq += __shfl_xor_sync(0xffffffffu, sq, o);
    if (lane == 0) red2[w] = sq;
    __syncthreads();
    float vtot = 0.f;
    #pragma unroll
    for (int i = 0; i < 8; i++) vtot += red2[i];
    float inv = rsqrtf(vtot * (1.0f / INDIM) + 1e-5f);

    float r0 = d0 * inv * gamma[t]       + beta[t];
    float r1 = d1 * inv * gamma[t + 256] + beta[t + 256];
    uint32_t h0, l0, h1, l1;
    split_tf32(r0, h0, l0);
    split_tf32(r1, h1, l1);
    size_t base = (size_t)m * INDIM;
    g_normed_hi[base + t]       = h0;
    g_normed_lo[base + t]       = l0;
    g_normed_hi[base + t + 256] = h1;
    g_normed_lo[base + t + 256] = l1;
}

// ============================================================
// Kernel 2/5: TF32x3 GEMM, cp.async double-buffered, 2 CTAs/SM
// C = A*B^T (+resid). Pre-split tf32 hi/lo operands.
// BM=BN=128, BK=16. Dynamic SMEM: 2 stages x 4 arrays x 128x20 words.
// ============================================================
#define TC_BM 128
#define TC_BN 128
#define TC_BK 16
#define STG_W (TC_BM * 20)            // words per array per stage
#define STAGE_W (4 * STG_W)           // words per stage
#define GEMM_SMEM_BYTES (2 * STAGE_W * 4)

template<bool RESID>
__global__ void __launch_bounds__(256, 2) mma_gemm_nt(
    const uint32_t* __restrict__ Ahg, const uint32_t* __restrict__ Alg,
    const uint32_t* __restrict__ Bhg, const uint32_t* __restrict__ Blg,
    float* __restrict__ C,
    const float* __restrict__ resid,
    int Ndim, int Kdim)
{
    extern __shared__ uint32_t sm[];

    const int tid    = threadIdx.x;
    const int lane   = tid & 31;
    const int wid    = tid >> 5;
    const int warp_m = wid & 3;
    const int warp_n = wid >> 2;
    const int g      = lane >> 2;
    const int tq     = lane & 3;
    const int mBase  = blockIdx.y * TC_BM;
    const int nBase  = blockIdx.x * TC_BN;

    const int lrow = tid >> 2;                // 0..63
    const int lc4  = (tid & 3) * 4;           // 0,4,8,12
    const uint32_t smBase = smem_u32(sm);

    float c[2][8][4];
    #pragma unroll
    for (int am = 0; am < 2; am++)
        #pragma unroll
        for (int an = 0; an < 8; an++)
            #pragma unroll
            for (int q = 0; q < 4; q++) c[am][an][q] = 0.f;

    const int NKB = Kdim / TC_BK;

    // ---- async tile-load of k-block kb into stage st ----
    auto issue_stage = [&](int kb, int st) {
        const int ko = kb * TC_BK;
        const uint32_t stB = smBase + (uint32_t)(st * STAGE_W) * 4u;
        #pragma unroll
        for (int it = 0; it < 2; it++) {
            int row = lrow + it * 64;
            uint32_t doff = ((uint32_t)(row * 20 + lc4)) * 4u;
            size_t aoff = (size_t)(mBase + row) * Kdim + ko + lc4;
            cp_async16(stB + doff,                 Ahg + aoff, 16);
            cp_async16(stB + (uint32_t)STG_W * 4u + doff, Alg + aoff, 16);
            int nrow = nBase + row;
            int nb   = (nrow < Ndim) ? 16 : 0;
            size_t boff = (size_t)((nrow < Ndim) ? nrow : 0) * Kdim + ko + lc4;
            cp_async16(stB + (uint32_t)(2 * STG_W) * 4u + doff, Bhg + boff, nb);
            cp_async16(stB + (uint32_t)(3 * STG_W) * 4u + doff, Blg + boff, nb);
        }
        CP_COMMIT();
    };

    issue_stage(0, 0);

    for (int kb = 0; kb < NKB; kb++) {
        if (kb + 1 < NKB) {
            issue_stage(kb + 1, (kb + 1) & 1);
            cp_wait<1>();
        } else {
            cp_wait<0>();
        }
        __syncthreads();

        const uint32_t* Ah = sm + (kb & 1) * STAGE_W;
        const uint32_t* Al = Ah + STG_W;
        const uint32_t* Bh = Al + STG_W;
        const uint32_t* Bl = Bh + STG_W;

        #pragma unroll
        for (int ks = 0; ks < 2; ks++) {
            const int kc = ks * 8 + tq;
            uint32_t ah[2][4], al[2][4];
            #pragma unroll
            for (int am = 0; am < 2; am++) {
                int r0 = (warp_m * 32 + am * 16 + g) * 20;
                ah[am][0] = Ah[r0 + kc];       ah[am][1] = Ah[r0 + 160 + kc];
                ah[am][2] = Ah[r0 + kc + 4];   ah[am][3] = Ah[r0 + 160 + kc + 4];
                al[am][0] = Al[r0 + kc];       al[am][1] = Al[r0 + 160 + kc];
                al[am][2] = Al[r0 + kc + 4];   al[am][3] = Al[r0 + 160 + kc + 4];
            }
            #pragma unroll
            for (int an = 0; an < 8; an++) {
                int n0 = (warp_n * 64 + an * 8 + g) * 20;
                uint32_t bh[2] = {Bh[n0 + kc], Bh[n0 + kc + 4]};
                uint32_t bl[2] = {Bl[n0 + kc], Bl[n0 + kc + 4]};
                #pragma unroll
                for (int am = 0; am < 2; am++) {
                    mma_tf32(c[am][an], ah[am], bh);
                    mma_tf32(c[am][an], al[am], bh);
                    mma_tf32(c[am][an], ah[am], bl);
                }
            }
        }
        __syncthreads();
    }

    #pragma unroll
    for (int am = 0; am < 2; am++) {
        int r0 = mBase + warp_m * 32 + am * 16 + g;
        #pragma unroll
        for (int an = 0; an < 8; an++) {
            int col = nBase + warp_n * 64 + an * 8 + 2 * tq;
            if (col < Ndim) {
                float2 v0 = make_float2(c[am][an][0], c[am][an][1]);
                float2 v1 = make_float2(c[am][an][2], c[am][an][3]);
                if (RESID) {
                    float2 q0 = *reinterpret_cast<const float2*>(
                        resid + (size_t)r0 * Ndim + col);
                    float2 q1 = *reinterpret_cast<const float2*>(
                        resid + (size_t)(r0 + 8) * Ndim + col);
                    v0.x += q0.x; v0.y += q0.y;
                    v1.x += q1.x; v1.y += q1.y;
                }
                *reinterpret_cast<float2*>(C + (size_t)r0 * Ndim + col) = v0;
                *reinterpret_cast<float2*>(C + (size_t)(r0 + 8) * Ndim + col) = v1;
            }
        }
    }
}

// ============================================================
// Kernel 3: per-head activations in place on g_qkvb
// ============================================================
__global__ void __launch_bounds__(256) act_kernel()
{
    int m    = blockIdx.x;
    int wp   = threadIdx.x >> 5;
    int lane = threadIdx.x & 31;
    float* base = g_qkvb + (size_t)m * PROJ + wp * PH;

    const int segs[3] = {0, 64, 192};
    #pragma unroll
    for (int si = 0; si < 3; si++) {
        int seg = segs[si];
        float a  = base[seg + lane];
        float bb = base[seg + 32 + lane];
        float mx = fmaxf(a, bb);
        #pragma unroll
        for (int o = 16; o; o >>= 1) mx = fmaxf(mx, __shfl_xor_sync(0xffffffffu, mx, o));
        float ea = __expf(a - mx);
        float eb = __expf(bb - mx);
        float s2 = ea + eb;
        #pragma unroll
        for (int o = 16; o; o >>= 1) s2 += __shfl_xor_sync(0xffffffffu, s2, o);
        float inv = 1.0f / s2;
        base[seg + lane]      = ea * inv;
        base[seg + 32 + lane] = eb * inv;
    }
    if (lane < 2) {
        float v = base[320 + lane];
        base[320 + lane] = 1.0f / (1.0f + __expf(-v));
    }
}

// ============================================================
// Kernel 4: sequential scan v3b (proven 330us) -> hs hi/lo
// ============================================================
__device__ __forceinline__ float dot32(const float* a, const float* __restrict__ b)
{
    float s0 = 0.f, s1 = 0.f, s2 = 0.f, s3 = 0.f;
    #pragma unroll
    for (int j = 0; j < 32; j += 4) {
        s0 = fmaf(a[j],     b[j],     s0);
        s1 = fmaf(a[j + 1], b[j + 1], s1);
        s2 = fmaf(a[j + 2], b[j + 2], s2);
        s3 = fmaf(a[j + 3], b[j + 3], s3);
    }
    return (s0 + s1) + (s2 + s3);
}

__device__ __forceinline__ void ld32(float* dst, const float* __restrict__ src)
{
    const float4* p = reinterpret_cast<const float4*>(src);
    #pragma unroll
    for (int q = 0; q < 8; q++) {
        float4 v = p[q];
        dst[q * 4 + 0] = v.x; dst[q * 4 + 1] = v.y;
        dst[q * 4 + 2] = v.z; dst[q * 4 + 3] = v.w;
    }
}

__global__ void __launch_bounds__(128) scan_kernel()
{
    int bh = blockIdx.x;
    int b = bh >> 3, h = bh & 7;
    int t    = threadIdx.x;
    int i    = t >> 1;
    int c    = t & 1;
    int lane = t & 31;
    int w    = t >> 5;

    __shared__ float buf[2][PHP];
    __shared__ float h_sh[2][64];
    __shared__ float e_sh[4][64];

    float W[32], R[32];
    #pragma unroll
    for (int j = 0; j < 32; j++) { W[j] = 0.f; R[j] = 0.f; }

    {
        const float* src = g_qkvb + (size_t)b * PROJ + h * PH;
        buf[0][t]       = src[t];
        buf[0][t + 128] = src[t + 128];
        if (t < PH - 256) buf[0][t + 256] = src[t + 256];
    }
    float p0, p1, p2 = 0.f;
    {
        const float* src = g_qkvb + (size_t)(BATCH + b) * PROJ + h * PH;
        p0 = src[t];
        p1 = src[t + 128];
        if (t < PH - 256) p2 = src[t + 256];
    }
    if (t < 64) { h_sh[0][t] = 0.f; h_sh[1][t] = 0.f; }
    __syncthreads();

    const int cofs = c * 32;

    for (int s = 0; s < S_LEN; s++) {
        {
            float* nb = buf[(s + 1) & 1];
            nb[t]       = p0;
            nb[t + 128] = p1;
            if (t < PH - 256) nb[t + 256] = p2;
        }
        if (s + 2 < S_LEN) {
            const float* src = g_qkvb + (size_t)((s + 2) * BATCH + b) * PROJ + h * PH;
            p0 = src[t];
            p1 = src[t + 128];
            if (t < PH - 256) p2 = src[t + 256];
        }

        const float* in = buf[s & 1];
        const float* hb = h_sh[s & 1];

        float h0 = hb[lane];
        float h1 = hb[lane + 32];
        float mx = fmaxf(h0, h1);
        #pragma unroll
        for (int o = 16; o; o >>= 1) mx = fmaxf(mx, __shfl_xor_sync(0xffffffffu, mx, o));
        float e0 = __expf(h0 - mx);
        float e1 = __expf(h1 - mx);
        e_sh[w][lane]      = e0;
        e_sh[w][lane + 32] = e1;
        float sm = e0 + e1;
        #pragma unroll
        for (int o = 16; o; o >>= 1) sm += __shfl_xor_sync(0xffffffffu, sm, o);
        float invTot = __fdividef(1.0f, sm);
        __syncwarp();

        float kreg[32];
        ld32(kreg, in + 64 + cofs);
        float vold = dot32(W, kreg);
        vold += __shfl_xor_sync(0xffffffffu, vold, 1);
        float coef = in[320] * (in[128 + i] - vold);
        #pragma unroll
        for (int j = 0; j < 32; j++) W[j] = fmaf(coef, kreg[j], W[j]);

        float qreg[32];
        ld32(qreg, in + cofs);
        float z = dot32(W, qreg);
        z += __shfl_xor_sync(0xffffffffu, z, 1);

        float rkreg[32];
        ld32(rkreg, in + 192 + cofs);
        float voldR = dot32(R, rkreg);
        voldR += __shfl_xor_sync(0xffffffffu, voldR, 1);
        float coefR = in[321] * (in[256 + i] - voldR);
        #pragma unroll
        for (int j = 0; j < 32; j++) R[j] = fmaf(coefR, rkreg[j], R[j]);

        float ereg[32];
        ld32(ereg, &e_sh[w][cofs]);
        float hd = dot32(R, ereg);
        hd += __shfl_xor_sync(0xffffffffu, hd, 1);
        float hn = z + hd * invTot;

        if (c == 0) {
            h_sh[(s + 1) & 1][i] = hn;
            uint32_t hi, lo;
            split_tf32(hn, hi, lo);
            size_t idx = (size_t)(s * BATCH + b) * OUTD + h * DHEAD + i;
            g_hs_hi[idx] = hi;
            g_hs_lo[idx] = lo;
        }
        __syncthreads();
    }
}

// ============================================================
// Launch
// ============================================================
extern "C" void kernel_launch(void* const* d_in, const int* in_sizes, int n_in,
                              void* d_out, int out_size)
{
    const float* x      = (const float*)d_in[0];
    const float* W_slow = (const float*)d_in[1];
    const float* W_out  = (const float*)d_in[2];
    const float* gamma  = (const float*)d_in[3];
    const float* betap  = (const float*)d_in[4];
    float* out = (float*)d_out;

    float*    p_qkvb = nullptr;
    uint32_t *p_nh = nullptr, *p_nl = nullptr, *p_hh = nullptr, *p_hl = nullptr;
    uint32_t *p_wsh = nullptr, *p_wsl = nullptr, *p_woh = nullptr, *p_wol = nullptr;
    cudaGetSymbolAddress((void**)&p_qkvb, g_qkvb);
    cudaGetSymbolAddress((void**)&p_nh,   g_normed_hi);
    cudaGetSymbolAddress((void**)&p_nl,   g_normed_lo);
    cudaGetSymbolAddress((void**)&p_hh,   g_hs_hi);
    cudaGetSymbolAddress((void**)&p_hl,   g_hs_lo);
    cudaGetSymbolAddress((void**)&p_wsh,  g_wslow_hi);
    cudaGetSymbolAddress((void**)&p_wsl,  g_wslow_lo);
    cudaGetSymbolAddress((void**)&p_woh,  g_wout_hi);
    cudaGetSymbolAddress((void**)&p_wol,  g_wout_lo);

    static bool attr_done = false;
    if (!attr_done) {
        cudaFuncSetAttribute((const void*)mma_gemm_nt<false>,
                             cudaFuncAttributeMaxDynamicSharedMemorySize,
                             GEMM_SMEM_BYTES);
        cudaFuncSetAttribute((const void*)mma_gemm_nt<true>,
                             cudaFuncAttributeMaxDynamicSharedMemorySize,
                             GEMM_SMEM_BYTES);
        attr_done = true;
    }

    // 0. split weights to tf32 hi/lo
    {
        int n1 = PROJ * INDIM;
        split_kernel<<<(n1 / 4 + 255) / 256, 256>>>(W_slow, p_wsh, p_wsl, n1);
        int n2 = INDIM * OUTD;
        split_kernel<<<(n2 / 4 + 255) / 256, 256>>>(W_out, p_woh, p_wol, n2);
    }

    // 1. LayerNorm -> tf32 hi/lo
    ln_kernel<<<MROWS, 256>>>(x, gamma, betap);

    // 2. qkvb = normed @ W_slow^T   (M=4096, N=2576, K=512)
    {
        dim3 grid((PROJ + TC_BN - 1) / TC_BN, MROWS / TC_BM);   // 21 x 32
        mma_gemm_nt<false><<<grid, 256, GEMM_SMEM_BYTES>>>(
            p_nh, p_nl, p_wsh, p_wsl, p_qkvb, nullptr, PROJ, INDIM);
    }

    // 3. softmax / sigmoid activations in place
    act_kernel<<<MROWS, 256>>>();

    // 4. sequential scan -> hs hi/lo
    scan_kernel<<<BATCH * HEADS, 128>>>();

    // 5. out = x + hs @ W_out^T     (M=4096, N=512, K=512)
    {
        dim3 grid(INDIM / TC_BN, MROWS / TC_BM);                // 4 x 32
        mma_gemm_nt<true><<<grid, 256, GEMM_SMEM_BYTES>>>(
            p_hh, p_hl, p_woh, p_wol, out, x, INDIM, OUTD);
    }
}

// round 11
// speedup vs baseline: 1.2982x; 1.0099x over previous
#include <cuda_runtime.h>
#include <cstdint>

#define S_LEN 512
#define BATCH 8
#define HEADS 8
#define DHEAD 64
#define INDIM 512
#define PH    322                 // 5*D + 2
#define PHP   324
#define PROJ  (HEADS * PH)        // 2576
#define MROWS (S_LEN * BATCH)     // 4096
#define OUTD  (HEADS * DHEAD)     // 512

typedef unsigned long long ull;

// ---- scratch (static device memory; no allocation at runtime) ----
__device__ float    g_qkvb[MROWS * PROJ];
__device__ uint32_t g_normed_hi[MROWS * INDIM];
__device__ uint32_t g_normed_lo[MROWS * INDIM];
__device__ uint32_t g_hs_hi[MROWS * OUTD];
__device__ uint32_t g_hs_lo[MROWS * OUTD];
__device__ uint32_t g_wslow_hi[PROJ * INDIM];
__device__ uint32_t g_wslow_lo[PROJ * INDIM];
__device__ uint32_t g_wout_hi[INDIM * OUTD];
__device__ uint32_t g_wout_lo[INDIM * OUTD];

// fp32 -> tf32 RN-even (integer path; plain-sm_103-safe)
__device__ __forceinline__ uint32_t f2tf32(float x)
{
    uint32_t u = __float_as_uint(x);
    u = (u + 0xFFFu + ((u >> 13) & 1u)) & 0xFFFFE000u;
    return u;
}
__device__ __forceinline__ void split_tf32(float x, uint32_t& hi, uint32_t& lo)
{
    hi = f2tf32(x);
    lo = f2tf32(x - __uint_as_float(hi));
}

// m16n8k8 tf32 tensor-core MMA
__device__ __forceinline__ void mma_tf32(float* c, const uint32_t* a, const uint32_t* b)
{
    asm volatile(
        "mma.sync.aligned.m16n8k8.row.col.f32.tf32.tf32.f32 "
        "{%0,%1,%2,%3}, {%4,%5,%6,%7}, {%8,%9}, {%0,%1,%2,%3};"
        : "+f"(c[0]), "+f"(c[1]), "+f"(c[2]), "+f"(c[3])
        : "r"(a[0]), "r"(a[1]), "r"(a[2]), "r"(a[3]), "r"(b[0]), "r"(b[1]));
}

// cp.async helpers (sm_80 feature; plain sm_103 OK)
__device__ __forceinline__ uint32_t smem_u32(const void* p)
{
    uint32_t a;
    asm("{ .reg .u64 t; cvta.to.shared.u64 t, %1; cvt.u32.u64 %0, t; }"
        : "=r"(a) : "l"(p));
    return a;
}
__device__ __forceinline__ void cp_async16(uint32_t dst, const void* src, int src_bytes)
{
    asm volatile("cp.async.cg.shared.global [%0], [%1], 16, %2;"
                 :: "r"(dst), "l"(src), "r"(src_bytes) : "memory");
}
#define CP_COMMIT() asm volatile("cp.async.commit_group;" ::: "memory")
template<int N>
__device__ __forceinline__ void cp_wait()
{
    asm volatile("cp.async.wait_group %0;" :: "n"(N) : "memory");
}

// ---- packed f32x2 helpers (Blackwell FFMA2; plain-sm_103-safe) ----
__device__ __forceinline__ ull fma_f32x2(ull a, ull b, ull c)
{
    ull d;
    asm("fma.rn.f32x2 %0, %1, %2, %3;" : "=l"(d) : "l"(a), "l"(b), "l"(c));
    return d;
}
__device__ __forceinline__ ull add_f32x2(ull a, ull b)
{
    ull d;
    asm("add.rn.f32x2 %0, %1, %2;" : "=l"(d) : "l"(a), "l"(b));
    return d;
}
__device__ __forceinline__ ull pack_dup(float x)
{
    ull d;
    asm("mov.b64 %0, {%1, %1};" : "=l"(d) : "f"(x));
    return d;
}
__device__ __forceinline__ void unpack2(ull v, float& lo, float& hi)
{
    asm("mov.b64 {%0, %1}, %2;" : "=f"(lo), "=f"(hi) : "l"(v));
}

// warp-wide float max via order-preserving int key + redux.sync (sm_80 instr)
__device__ __forceinline__ float warp_max_f32(float x)
{
    uint32_t b = __float_as_uint(x);
    uint32_t s = (uint32_t)((int32_t)b >> 31);
    uint32_t key = b ^ (s | 0x80000000u);
    uint32_t m;
    asm("redux.sync.max.u32 %0, %1, 0xffffffff;" : "=r"(m) : "r"(key));
    uint32_t mask = (m & 0x80000000u) ? 0x80000000u : 0xFFFFFFFFu;
    return __uint_as_float(m ^ mask);
}

// ============================================================
// Kernel 0: weight split (fp32 -> tf32 hi/lo)
// ============================================================
__global__ void __launch_bounds__(256) split_kernel(
    const float* __restrict__ src, uint32_t* __restrict__ dst_hi,
    uint32_t* __restrict__ dst_lo, int n)
{
    int idx = (blockIdx.x * 256 + threadIdx.x) * 4;
    if (idx < n) {
        float4 v = *reinterpret_cast<const float4*>(src + idx);
        uint4 h, l;
        split_tf32(v.x, h.x, l.x);
        split_tf32(v.y, h.y, l.y);
        split_tf32(v.z, h.z, l.z);
        split_tf32(v.w, h.w, l.w);
        *reinterpret_cast<uint4*>(dst_hi + idx) = h;
        *reinterpret_cast<uint4*>(dst_lo + idx) = l;
    }
}

// ============================================================
// Kernel 1: LayerNorm -> tf32 hi/lo
// ============================================================
__global__ void __launch_bounds__(256) ln_kernel(
    const float* __restrict__ x,
    const float* __restrict__ gamma,
    const float* __restrict__ beta)
{
    int m = blockIdx.x;
    int t = threadIdx.x;
    const float* row = x + (size_t)m * INDIM;
    float v0 = row[t];
    float v1 = row[t + 256];

    float s = v0 + v1;
    #pragma unroll
    for (int o = 16; o; o >>= 1) s += __shfl_xor_sync(0xffffffffu, s, o);

    __shared__ float red[8];
    __shared__ float red2[8];
    int w = t >> 5, lane = t & 31;
    if (lane == 0) red[w] = s;
    __syncthreads();
    float tot = 0.f;
    #pragma unroll
    for (int i = 0; i < 8; i++) tot += red[i];
    float mean = tot * (1.0f / INDIM);

    float d0 = v0 - mean, d1 = v1 - mean;
    float sq = d0 * d0 + d1 * d1;
    #pragma unroll
    for (int o = 16; o; o >>= 1) sq += __shfl_xor_sync(0xffffffffu, sq, o);
    if (lane == 0) red2[w] = sq;
    __syncthreads();
    float vtot = 0.f;
    #pragma unroll
    for (int i = 0; i < 8; i++) vtot += red2[i];
    float inv = rsqrtf(vtot * (1.0f / INDIM) + 1e-5f);

    float r0 = d0 * inv * gamma[t]       + beta[t];
    float r1 = d1 * inv * gamma[t + 256] + beta[t + 256];
    uint32_t h0, l0, h1, l1;
    split_tf32(r0, h0, l0);
    split_tf32(r1, h1, l1);
    size_t base = (size_t)m * INDIM;
    g_normed_hi[base + t]       = h0;
    g_normed_lo[base + t]       = l0;
    g_normed_hi[base + t + 256] = h1;
    g_normed_lo[base + t + 256] = l1;
}

// ============================================================
// Kernel 2/5: TF32x3 GEMM, 4-stage cp.async, BK=8, 1 sync/iter
// C = A*B^T (+resid). Pre-split tf32 hi/lo operands.
// ============================================================
#define TC_BM 128
#define TC_BN 128
#define TC_BK 8
#define ROWW  12                          // words per SMEM row (12g%32 = 4Z: conflict-free)
#define STG_W   (TC_BM * ROWW)            // 1536 words per array
#define STAGE_W (4 * STG_W)               // 6144 words per stage
#define NSTAGE  4
#define GEMM_SMEM_BYTES (NSTAGE * STAGE_W * 4)   // 98304

template<bool RESID>
__global__ void __launch_bounds__(256, 2) mma_gemm_nt(
    const uint32_t* __restrict__ Ahg, const uint32_t* __restrict__ Alg,
    const uint32_t* __restrict__ Bhg, const uint32_t* __restrict__ Blg,
    float* __restrict__ C,
    const float* __restrict__ resid,
    int Ndim, int Kdim)
{
    extern __shared__ uint32_t sm[];

    const int tid    = threadIdx.x;
    const int lane   = tid & 31;
    const int wid    = tid >> 5;
    const int warp_m = wid & 3;
    const int warp_n = wid >> 2;
    const int g      = lane >> 2;
    const int tq     = lane & 3;
    const int mBase  = blockIdx.y * TC_BM;
    const int nBase  = blockIdx.x * TC_BN;

    const int lrow = tid >> 1;            // 0..127
    const int lc4  = (tid & 1) * 4;       // 0 or 4
    const uint32_t smBase = smem_u32(sm);

    float c[2][8][4];
    #pragma unroll
    for (int am = 0; am < 2; am++)
        #pragma unroll
        for (int an = 0; an < 8; an++)
            #pragma unroll
            for (int q = 0; q < 4; q++) c[am][an][q] = 0.f;

    const int NKB = Kdim / TC_BK;         // 64

    const int  nrow  = nBase + lrow;
    const int  nb    = (nrow < Ndim) ? 16 : 0;
    const size_t aRow = (size_t)(mBase + lrow) * Kdim + lc4;
    const size_t bRow = (size_t)((nrow < Ndim) ? nrow : 0) * Kdim + lc4;
    const uint32_t doff = ((uint32_t)(lrow * ROWW + lc4)) * 4u;

    auto issue_stage = [&](int kb, int st) {
        const int ko = kb * TC_BK;
        const uint32_t stB = smBase + (uint32_t)(st * STAGE_W) * 4u + doff;
        cp_async16(stB,                                Ahg + aRow + ko, 16);
        cp_async16(stB + (uint32_t)STG_W * 4u,         Alg + aRow + ko, 16);
        cp_async16(stB + (uint32_t)(2 * STG_W) * 4u,   Bhg + bRow + ko, nb);
        cp_async16(stB + (uint32_t)(3 * STG_W) * 4u,   Blg + bRow + ko, nb);
        CP_COMMIT();
    };

    issue_stage(0, 0);
    issue_stage(1, 1);
    issue_stage(2, 2);

    for (int kb = 0; kb < NKB; kb++) {
        cp_wait<2>();
        __syncthreads();

        const uint32_t* Ah = sm + (kb & 3) * STAGE_W;
        const uint32_t* Al = Ah + STG_W;
        const uint32_t* Bh = Al + STG_W;
        const uint32_t* Bl = Bh + STG_W;

        uint32_t ah[2][4], al[2][4];
        #pragma unroll
        for (int am = 0; am < 2; am++) {
            int r0 = (warp_m * 32 + am * 16 + g) * ROWW;
            ah[am][0] = Ah[r0 + tq];             ah[am][1] = Ah[r0 + 8 * ROWW + tq];
            ah[am][2] = Ah[r0 + tq + 4];         ah[am][3] = Ah[r0 + 8 * ROWW + tq + 4];
            al[am][0] = Al[r0 + tq];             al[am][1] = Al[r0 + 8 * ROWW + tq];
            al[am][2] = Al[r0 + tq + 4];         al[am][3] = Al[r0 + 8 * ROWW + tq + 4];
        }
        #pragma unroll
        for (int an = 0; an < 8; an++) {
            int n0 = (warp_n * 64 + an * 8 + g) * ROWW;
            uint32_t bh[2] = {Bh[n0 + tq], Bh[n0 + tq + 4]};
            uint32_t bl[2] = {Bl[n0 + tq], Bl[n0 + tq + 4]};
            #pragma unroll
            for (int am = 0; am < 2; am++) {
                mma_tf32(c[am][an], ah[am], bh);
                mma_tf32(c[am][an], al[am], bh);
                mma_tf32(c[am][an], ah[am], bl);
            }
        }

        if (kb + 3 < NKB) issue_stage(kb + 3, (kb + 3) & 3);
    }

    #pragma unroll
    for (int am = 0; am < 2; am++) {
        int r0 = mBase + warp_m * 32 + am * 16 + g;
        #pragma unroll
        for (int an = 0; an < 8; an++) {
            int col = nBase + warp_n * 64 + an * 8 + 2 * tq;
            if (col < Ndim) {
                float2 v0 = make_float2(c[am][an][0], c[am][an][1]);
                float2 v1 = make_float2(c[am][an][2], c[am][an][3]);
                if (RESID) {
                    float2 q0 = *reinterpret_cast<const float2*>(
                        resid + (size_t)r0 * Ndim + col);
                    float2 q1 = *reinterpret_cast<const float2*>(
                        resid + (size_t)(r0 + 8) * Ndim + col);
                    v0.x += q0.x; v0.y += q0.y;
                    v1.x += q1.x; v1.y += q1.y;
                }
                *reinterpret_cast<float2*>(C + (size_t)r0 * Ndim + col) = v0;
                *reinterpret_cast<float2*>(C + (size_t)(r0 + 8) * Ndim + col) = v1;
            }
        }
    }
}

// ============================================================
// Kernel 3: per-head activations in place on g_qkvb
// ============================================================
__global__ void __launch_bounds__(256) act_kernel()
{
    int m    = blockIdx.x;
    int wp   = threadIdx.x >> 5;
    int lane = threadIdx.x & 31;
    float* base = g_qkvb + (size_t)m * PROJ + wp * PH;

    const int segs[3] = {0, 64, 192};
    #pragma unroll
    for (int si = 0; si < 3; si++) {
        int seg = segs[si];
        float a  = base[seg + lane];
        float bb = base[seg + 32 + lane];
        float mx = warp_max_f32(fmaxf(a, bb));
        float ea = __expf(a - mx);
        float eb = __expf(bb - mx);
        float s2 = ea + eb;
        #pragma unroll
        for (int o = 16; o; o >>= 1) s2 += __shfl_xor_sync(0xffffffffu, s2, o);
        float inv = 1.0f / s2;
        base[seg + lane]      = ea * inv;
        base[seg + 32 + lane] = eb * inv;
    }
    if (lane < 2) {
        float v = base[320 + lane];
        base[320 + lane] = 1.0f / (1.0f + __expf(-v));
    }
}

// ============================================================
// Kernel 4: sequential scan v6 = v3b + packed f32x2 + redux max
// 64 CTAs, 128 threads, 2 threads/row, one barrier/step.
// ============================================================
__device__ __forceinline__ void ld16p(ull* dst, const float* __restrict__ src)
{
    const ulonglong2* p = reinterpret_cast<const ulonglong2*>(src);
    #pragma unroll
    for (int q = 0; q < 8; q++) {
        ulonglong2 v = p[q];
        dst[q * 2]     = v.x;
        dst[q * 2 + 1] = v.y;
    }
}

__device__ __forceinline__ float dot16p(const ull* a, const ull* b)
{
    ull s0 = 0ull, s1 = 0ull, s2 = 0ull, s3 = 0ull;
    #pragma unroll
    for (int j = 0; j < 16; j += 4) {
        s0 = fma_f32x2(a[j],     b[j],     s0);
        s1 = fma_f32x2(a[j + 1], b[j + 1], s1);
        s2 = fma_f32x2(a[j + 2], b[j + 2], s2);
        s3 = fma_f32x2(a[j + 3], b[j + 3], s3);
    }
    ull tt = add_f32x2(add_f32x2(s0, s1), add_f32x2(s2, s3));
    float lo, hi;
    unpack2(tt, lo, hi);
    return lo + hi;
}

__global__ void __launch_bounds__(128) scan_kernel()
{
    int bh = blockIdx.x;
    int b = bh >> 3, h = bh & 7;
    int t    = threadIdx.x;
    int i    = t >> 1;
    int c    = t & 1;
    int lane = t & 31;
    int w    = t >> 5;

    __shared__ __align__(16) float buf[2][PHP];
    __shared__ float h_sh[2][64];
    __shared__ __align__(16) float e_sh[4][64];

    ull W2[16], R2[16];
    #pragma unroll
    for (int j = 0; j < 16; j++) { W2[j] = 0ull; R2[j] = 0ull; }

    {
        const float* src = g_qkvb + (size_t)b * PROJ + h * PH;
        buf[0][t]       = src[t];
        buf[0][t + 128] = src[t + 128];
        if (t < PH - 256) buf[0][t + 256] = src[t + 256];
    }
    float p0, p1, p2 = 0.f;
    {
        const float* src = g_qkvb + (size_t)(BATCH + b) * PROJ + h * PH;
        p0 = src[t];
        p1 = src[t + 128];
        if (t < PH - 256) p2 = src[t + 256];
    }
    if (t < 64) { h_sh[0][t] = 0.f; h_sh[1][t] = 0.f; }
    __syncthreads();

    const int cofs = c * 32;

    for (int s = 0; s < S_LEN; s++) {
        // early-commit prefetched inputs for step s+1
        {
            float* nb = buf[(s + 1) & 1];
            nb[t]       = p0;
            nb[t + 128] = p1;
            if (t < PH - 256) nb[t + 256] = p2;
        }
        // issue prefetch for step s+2
        if (s + 2 < S_LEN) {
            const float* src = g_qkvb + (size_t)((s + 2) * BATCH + b) * PROJ + h * PH;
            p0 = src[t];
            p1 = src[t + 128];
            if (t < PH - 256) p2 = src[t + 256];
        }

        const float* in = buf[s & 1];
        const float* hb = h_sh[s & 1];

        // softmax(h_prev): redundant per warp; single-instr max reduction
        float h0 = hb[lane];
        float h1 = hb[lane + 32];
        float mx = warp_max_f32(fmaxf(h0, h1));
        float e0 = __expf(h0 - mx);
        float e1 = __expf(h1 - mx);
        e_sh[w][lane]      = e0;
        e_sh[w][lane + 32] = e1;
        float sm = e0 + e1;                      // sum chain hidden under W branch
        #pragma unroll
        for (int o = 16; o; o >>= 1) sm += __shfl_xor_sync(0xffffffffu, sm, o);
        float invTot = __fdividef(1.0f, sm);
        __syncwarp();

        // delta-rule fast weight W (packed f32x2)
        ull k2[16];
        ld16p(k2, in + 64 + cofs);
        float vold = dot16p(W2, k2);
        vold += __shfl_xor_sync(0xffffffffu, vold, 1);
        float coef = in[320] * (in[128 + i] - vold);
        ull cd = pack_dup(coef);
        #pragma unroll
        for (int j = 0; j < 16; j++) W2[j] = fma_f32x2(cd, k2[j], W2[j]);

        ull q2[16];
        ld16p(q2, in + cofs);
        float z = dot16p(W2, q2);
        z += __shfl_xor_sync(0xffffffffu, z, 1);

        // fast RNN R (packed f32x2)
        ull rk2[16];
        ld16p(rk2, in + 192 + cofs);
        float voldR = dot16p(R2, rk2);
        voldR += __shfl_xor_sync(0xffffffffu, voldR, 1);
        float coefR = in[321] * (in[256 + i] - voldR);
        ull crd = pack_dup(coefR);
        #pragma unroll
        for (int j = 0; j < 16; j++) R2[j] = fma_f32x2(crd, rk2[j], R2[j]);

        ull er2[16];
        ld16p(er2, &e_sh[w][cofs]);
        float hd = dot16p(R2, er2);
        hd += __shfl_xor_sync(0xffffffffu, hd, 1);
        float hn = z + hd * invTot;

        if (c == 0) {
            h_sh[(s + 1) & 1][i] = hn;
            uint32_t hi, lo;
            split_tf32(hn, hi, lo);
            size_t idx = (size_t)(s * BATCH + b) * OUTD + h * DHEAD + i;
            g_hs_hi[idx] = hi;
            g_hs_lo[idx] = lo;
        }
        __syncthreads();
    }
}

// ============================================================
// Launch
// ============================================================
extern "C" void kernel_launch(void* const* d_in, const int* in_sizes, int n_in,
                              void* d_out, int out_size)
{
    const float* x      = (const float*)d_in[0];
    const float* W_slow = (const float*)d_in[1];
    const float* W_out  = (const float*)d_in[2];
    const float* gamma  = (const float*)d_in[3];
    const float* betap  = (const float*)d_in[4];
    float* out = (float*)d_out;

    float*    p_qkvb = nullptr;
    uint32_t *p_nh = nullptr, *p_nl = nullptr, *p_hh = nullptr, *p_hl = nullptr;
    uint32_t *p_wsh = nullptr, *p_wsl = nullptr, *p_woh = nullptr, *p_wol = nullptr;
    cudaGetSymbolAddress((void**)&p_qkvb, g_qkvb);
    cudaGetSymbolAddress((void**)&p_nh,   g_normed_hi);
    cudaGetSymbolAddress((void**)&p_nl,   g_normed_lo);
    cudaGetSymbolAddress((void**)&p_hh,   g_hs_hi);
    cudaGetSymbolAddress((void**)&p_hl,   g_hs_lo);
    cudaGetSymbolAddress((void**)&p_wsh,  g_wslow_hi);
    cudaGetSymbolAddress((void**)&p_wsl,  g_wslow_lo);
    cudaGetSymbolAddress((void**)&p_woh,  g_wout_hi);
    cudaGetSymbolAddress((void**)&p_wol,  g_wout_lo);

    static bool attr_done = false;
    if (!attr_done) {
        cudaFuncSetAttribute((const void*)mma_gemm_nt<false>,
                             cudaFuncAttributeMaxDynamicSharedMemorySize,
                             GEMM_SMEM_BYTES);
        cudaFuncSetAttribute((const void*)mma_gemm_nt<true>,
                             cudaFuncAttributeMaxDynamicSharedMemorySize,
                             GEMM_SMEM_BYTES);
        attr_done = true;
    }

    // 0. split weights to tf32 hi/lo
    {
        int n1 = PROJ * INDIM;
        split_kernel<<<(n1 / 4 + 255) / 256, 256>>>(W_slow, p_wsh, p_wsl, n1);
        int n2 = INDIM * OUTD;
        split_kernel<<<(n2 / 4 + 255) / 256, 256>>>(W_out, p_woh, p_wol, n2);
    }

    // 1. LayerNorm -> tf32 hi/lo
    ln_kernel<<<MROWS, 256>>>(x, gamma, betap);

    // 2. qkvb = normed @ W_slow^T   (M=4096, N=2576, K=512)
    {
        dim3 grid((PROJ + TC_BN - 1) / TC_BN, MROWS / TC_BM);   // 21 x 32
        mma_gemm_nt<false><<<grid, 256, GEMM_SMEM_BYTES>>>(
            p_nh, p_nl, p_wsh, p_wsl, p_qkvb, nullptr, PROJ, INDIM);
    }

    // 3. softmax / sigmoid activations in place
    act_kernel<<<MROWS, 256>>>();

    // 4. sequential scan -> hs hi/lo
    scan_kernel<<<BATCH * HEADS, 128>>>();

    // 5. out = x + hs @ W_out^T     (M=4096, N=512, K=512)
    {
        dim3 grid(INDIM / TC_BN, MROWS / TC_BM);                // 4 x 32
        mma_gemm_nt<true><<<grid, 256, GEMM_SMEM_BYTES>>>(
            p_hh, p_hl, p_woh, p_wol, out, x, INDIM, OUTD);
    }
}

// round 12
// speedup vs baseline: 1.3853x; 1.0671x over previous
#include <cuda_runtime.h>
#include <cstdint>

#define S_LEN 512
#define BATCH 8
#define HEADS 8
#define DHEAD 64
#define INDIM 512
#define PH    322                 // 5*D + 2
#define PHP   324
#define PROJ  (HEADS * PH)        // 2576
#define MROWS (S_LEN * BATCH)     // 4096
#define OUTD  (HEADS * DHEAD)     // 512

typedef unsigned long long ull;

// ---- scratch (static device memory; no allocation at runtime) ----
__device__ float    g_qkvb[MROWS * PROJ];
__device__ uint32_t g_normed_hi[MROWS * INDIM];
__device__ uint32_t g_normed_lo[MROWS * INDIM];
__device__ uint32_t g_hs_hi[MROWS * OUTD];
__device__ uint32_t g_hs_lo[MROWS * OUTD];
__device__ uint32_t g_wslow_hi[PROJ * INDIM];
__device__ uint32_t g_wslow_lo[PROJ * INDIM];
__device__ uint32_t g_wout_hi[INDIM * OUTD];
__device__ uint32_t g_wout_lo[INDIM * OUTD];

// fp32 -> tf32 RN-even (integer path; plain-sm_103-safe)
__device__ __forceinline__ uint32_t f2tf32(float x)
{
    uint32_t u = __float_as_uint(x);
    u = (u + 0xFFFu + ((u >> 13) & 1u)) & 0xFFFFE000u;
    return u;
}
__device__ __forceinline__ void split_tf32(float x, uint32_t& hi, uint32_t& lo)
{
    hi = f2tf32(x);
    lo = f2tf32(x - __uint_as_float(hi));
}

// m16n8k8 tf32 tensor-core MMA
__device__ __forceinline__ void mma_tf32(float* c, const uint32_t* a, const uint32_t* b)
{
    asm volatile(
        "mma.sync.aligned.m16n8k8.row.col.f32.tf32.tf32.f32 "
        "{%0,%1,%2,%3}, {%4,%5,%6,%7}, {%8,%9}, {%0,%1,%2,%3};"
        : "+f"(c[0]), "+f"(c[1]), "+f"(c[2]), "+f"(c[3])
        : "r"(a[0]), "r"(a[1]), "r"(a[2]), "r"(a[3]), "r"(b[0]), "r"(b[1]));
}

// ldmatrix x4 (sm_75+; plain sm_103 OK). b16 8x8 matrix == tf32 8x4 block.
__device__ __forceinline__ void ldsm_x4(uint32_t* r, uint32_t addr)
{
    asm volatile("ldmatrix.sync.aligned.m8n8.x4.shared.b16 {%0,%1,%2,%3}, [%4];"
        : "=r"(r[0]), "=r"(r[1]), "=r"(r[2]), "=r"(r[3]) : "r"(addr));
}

// cp.async helpers (sm_80 feature; plain sm_103 OK)
__device__ __forceinline__ uint32_t smem_u32(const void* p)
{
    uint32_t a;
    asm("{ .reg .u64 t; cvta.to.shared.u64 t, %1; cvt.u32.u64 %0, t; }"
        : "=r"(a) : "l"(p));
    return a;
}
__device__ __forceinline__ void cp_async16(uint32_t dst, const void* src, int src_bytes)
{
    asm volatile("cp.async.cg.shared.global [%0], [%1], 16, %2;"
                 :: "r"(dst), "l"(src), "r"(src_bytes) : "memory");
}
#define CP_COMMIT() asm volatile("cp.async.commit_group;" ::: "memory")
template<int N>
__device__ __forceinline__ void cp_wait()
{
    asm volatile("cp.async.wait_group %0;" :: "n"(N) : "memory");
}

// ---- packed f32x2 helpers (Blackwell FFMA2; plain-sm_103-safe) ----
__device__ __forceinline__ ull fma_f32x2(ull a, ull b, ull c)
{
    ull d;
    asm("fma.rn.f32x2 %0, %1, %2, %3;" : "=l"(d) : "l"(a), "l"(b), "l"(c));
    return d;
}
__device__ __forceinline__ ull add_f32x2(ull a, ull b)
{
    ull d;
    asm("add.rn.f32x2 %0, %1, %2;" : "=l"(d) : "l"(a), "l"(b));
    return d;
}
__device__ __forceinline__ ull pack_dup(float x)
{
    ull d;
    asm("mov.b64 %0, {%1, %1};" : "=l"(d) : "f"(x));
    return d;
}
__device__ __forceinline__ void unpack2(ull v, float& lo, float& hi)
{
    asm("mov.b64 {%0, %1}, %2;" : "=f"(lo), "=f"(hi) : "l"(v));
}

// warp-wide float max via order-preserving int key + redux.sync (sm_80 instr)
__device__ __forceinline__ float warp_max_f32(float x)
{
    uint32_t b = __float_as_uint(x);
    uint32_t s = (uint32_t)((int32_t)b >> 31);
    uint32_t key = b ^ (s | 0x80000000u);
    uint32_t m;
    asm("redux.sync.max.u32 %0, %1, 0xffffffff;" : "=r"(m) : "r"(key));
    uint32_t mask = (m & 0x80000000u) ? 0x80000000u : 0xFFFFFFFFu;
    return __uint_as_float(m ^ mask);
}

// ============================================================
// Kernel 0: weight split (fp32 -> tf32 hi/lo)
// ============================================================
__global__ void __launch_bounds__(256) split_kernel(
    const float* __restrict__ src, uint32_t* __restrict__ dst_hi,
    uint32_t* __restrict__ dst_lo, int n)
{
    int idx = (blockIdx.x * 256 + threadIdx.x) * 4;
    if (idx < n) {
        float4 v = *reinterpret_cast<const float4*>(src + idx);
        uint4 h, l;
        split_tf32(v.x, h.x, l.x);
        split_tf32(v.y, h.y, l.y);
        split_tf32(v.z, h.z, l.z);
        split_tf32(v.w, h.w, l.w);
        *reinterpret_cast<uint4*>(dst_hi + idx) = h;
        *reinterpret_cast<uint4*>(dst_lo + idx) = l;
    }
}

// ============================================================
// Kernel 1: LayerNorm -> tf32 hi/lo
// ============================================================
__global__ void __launch_bounds__(256) ln_kernel(
    const float* __restrict__ x,
    const float* __restrict__ gamma,
    const float* __restrict__ beta)
{
    int m = blockIdx.x;
    int t = threadIdx.x;
    const float* row = x + (size_t)m * INDIM;
    float v0 = row[t];
    float v1 = row[t + 256];

    float s = v0 + v1;
    #pragma unroll
    for (int o = 16; o; o >>= 1) s += __shfl_xor_sync(0xffffffffu, s, o);

    __shared__ float red[8];
    __shared__ float red2[8];
    int w = t >> 5, lane = t & 31;
    if (lane == 0) red[w] = s;
    __syncthreads();
    float tot = 0.f;
    #pragma unroll
    for (int i = 0; i < 8; i++) tot += red[i];
    float mean = tot * (1.0f / INDIM);

    float d0 = v0 - mean, d1 = v1 - mean;
    float sq = d0 * d0 + d1 * d1;
    #pragma unroll
    for (int o = 16; o; o >>= 1) sq += __shfl_xor_sync(0xffffffffu, sq, o);
    if (lane == 0) red2[w] = sq;
    __syncthreads();
    float vtot = 0.f;
    #pragma unroll
    for (int i = 0; i < 8; i++) vtot += red2[i];
    float inv = rsqrtf(vtot * (1.0f / INDIM) + 1e-5f);

    float r0 = d0 * inv * gamma[t]       + beta[t];
    float r1 = d1 * inv * gamma[t + 256] + beta[t + 256];
    uint32_t h0, l0, h1, l1;
    split_tf32(r0, h0, l0);
    split_tf32(r1, h1, l1);
    size_t base = (size_t)m * INDIM;
    g_normed_hi[base + t]       = h0;
    g_normed_lo[base + t]       = l0;
    g_normed_hi[base + t + 256] = h1;
    g_normed_lo[base + t + 256] = l1;
}

// ============================================================
// Kernel 2/5: TF32x3 GEMM, 4-stage cp.async, BK=8, ldmatrix frags
// C = A*B^T (+resid). Pre-split tf32 hi/lo operands.
// ============================================================
#define TC_BM 128
#define TC_BN 128
#define TC_BK 8
#define ROWW  12                          // words/row; rows hit distinct 16B banks
#define STG_W   (TC_BM * ROWW)            // 1536 words per array
#define STAGE_W (4 * STG_W)               // 6144 words per stage
#define NSTAGE  4
#define GEMM_SMEM_BYTES (NSTAGE * STAGE_W * 4)   // 98304

template<bool RESID>
__global__ void __launch_bounds__(256, 2) mma_gemm_nt(
    const uint32_t* __restrict__ Ahg, const uint32_t* __restrict__ Alg,
    const uint32_t* __restrict__ Bhg, const uint32_t* __restrict__ Blg,
    float* __restrict__ C,
    const float* __restrict__ resid,
    int Ndim, int Kdim)
{
    extern __shared__ uint32_t sm[];

    const int tid    = threadIdx.x;
    const int lane   = tid & 31;
    const int wid    = tid >> 5;
    const int warp_m = wid & 3;
    const int warp_n = wid >> 2;
    const int g      = lane >> 2;
    const int tq     = lane & 3;
    const int mBase  = blockIdx.y * TC_BM;
    const int nBase  = blockIdx.x * TC_BN;

    const int lrow = tid >> 1;            // 0..127
    const int lc4  = (tid & 1) * 4;       // 0 or 4
    const uint32_t smBase = smem_u32(sm);

    float c[2][8][4];
    #pragma unroll
    for (int am = 0; am < 2; am++)
        #pragma unroll
        for (int an = 0; an < 8; an++)
            #pragma unroll
            for (int q = 0; q < 4; q++) c[am][an][q] = 0.f;

    const int NKB = Kdim / TC_BK;         // 64

    const int  nrow  = nBase + lrow;
    const int  nb    = (nrow < Ndim) ? 16 : 0;
    const size_t aRow = (size_t)(mBase + lrow) * Kdim + lc4;
    const size_t bRow = (size_t)((nrow < Ndim) ? nrow : 0) * Kdim + lc4;
    const uint32_t doff = ((uint32_t)(lrow * ROWW + lc4)) * 4u;

    auto issue_stage = [&](int kb, int st) {
        const int ko = kb * TC_BK;
        const uint32_t stB = smBase + (uint32_t)(st * STAGE_W) * 4u + doff;
        cp_async16(stB,                                Ahg + aRow + ko, 16);
        cp_async16(stB + (uint32_t)STG_W * 4u,         Alg + aRow + ko, 16);
        cp_async16(stB + (uint32_t)(2 * STG_W) * 4u,   Bhg + bRow + ko, nb);
        cp_async16(stB + (uint32_t)(3 * STG_W) * 4u,   Blg + bRow + ko, nb);
        CP_COMMIT();
    };

    issue_stage(0, 0);
    issue_stage(1, 1);
    issue_stage(2, 2);

    // ---- per-lane ldmatrix addresses (byte offsets within a stage) ----
    // A m-tile fragment (m16k8): matrix idx mm = lane>>3; row = lane&7.
    //   row_add = (mm&1)*8, col_words = (mm>>1)*4
    const int mm  = lane >> 3;
    const int mr  = lane & 7;
    const int aRowSel = mr + (mm & 1) * 8;
    const int aColSel = (mm >> 1) * 4;
    uint32_t offA[2];       // hi offsets for m-tile 0/1 (lo = +STG_W*4)
    #pragma unroll
    for (int am = 0; am < 2; am++)
        offA[am] = (uint32_t)(((warp_m * 32 + am * 16 + aRowSel) * ROWW + aColSel) * 4);
    // B n-tile pair fragment: matrices (an, an|cols4-7, an+1, an+1|cols4-7)
    //   tile_add = (mm>>1)*8 rows within pair; col_words = (mm&1)*4
    uint32_t offB[4];       // hi offsets for pair p -> tiles 2p,2p+1
    #pragma unroll
    for (int p = 0; p < 4; p++) {
        int nr = warp_n * 64 + (2 * p + (mm >> 1)) * 8 + mr;
        offB[p] = (uint32_t)((nr * ROWW + (mm & 1) * 4) * 4) + (uint32_t)(2 * STG_W) * 4u;
    }

    for (int kb = 0; kb < NKB; kb++) {
        cp_wait<2>();
        __syncthreads();

        const uint32_t stB = smBase + (uint32_t)((kb & 3) * STAGE_W) * 4u;
        const uint32_t loOff = (uint32_t)STG_W * 4u;

        uint32_t ah[2][4], al[2][4];
        #pragma unroll
        for (int am = 0; am < 2; am++) {
            ldsm_x4(ah[am], stB + offA[am]);
            ldsm_x4(al[am], stB + offA[am] + loOff);
        }
        uint32_t bh[8][2], bl[8][2];
        #pragma unroll
        for (int p = 0; p < 4; p++) {
            uint32_t rh[4], rl[4];
            ldsm_x4(rh, stB + offB[p]);
            ldsm_x4(rl, stB + offB[p] + loOff);
            bh[2 * p][0] = rh[0]; bh[2 * p][1] = rh[1];
            bh[2 * p + 1][0] = rh[2]; bh[2 * p + 1][1] = rh[3];
            bl[2 * p][0] = rl[0]; bl[2 * p][1] = rl[1];
            bl[2 * p + 1][0] = rl[2]; bl[2 * p + 1][1] = rl[3];
        }

        #pragma unroll
        for (int an = 0; an < 8; an++)
            #pragma unroll
            for (int am = 0; am < 2; am++) {
                mma_tf32(c[am][an], ah[am], bh[an]);
                mma_tf32(c[am][an], al[am], bh[an]);
                mma_tf32(c[am][an], ah[am], bl[an]);
            }

        if (kb + 3 < NKB) issue_stage(kb + 3, (kb + 3) & 3);
    }

    #pragma unroll
    for (int am = 0; am < 2; am++) {
        int r0 = mBase + warp_m * 32 + am * 16 + g;
        #pragma unroll
        for (int an = 0; an < 8; an++) {
            int col = nBase + warp_n * 64 + an * 8 + 2 * tq;
            if (col < Ndim) {
                float2 v0 = make_float2(c[am][an][0], c[am][an][1]);
                float2 v1 = make_float2(c[am][an][2], c[am][an][3]);
                if (RESID) {
                    float2 q0 = *reinterpret_cast<const float2*>(
                        resid + (size_t)r0 * Ndim + col);
                    float2 q1 = *reinterpret_cast<const float2*>(
                        resid + (size_t)(r0 + 8) * Ndim + col);
                    v0.x += q0.x; v0.y += q0.y;
                    v1.x += q1.x; v1.y += q1.y;
                }
                *reinterpret_cast<float2*>(C + (size_t)r0 * Ndim + col) = v0;
                *reinterpret_cast<float2*>(C + (size_t)(r0 + 8) * Ndim + col) = v1;
            }
        }
    }
}

// ============================================================
// Kernel 3: per-head activations in place on g_qkvb
// ============================================================
__global__ void __launch_bounds__(256) act_kernel()
{
    int m    = blockIdx.x;
    int wp   = threadIdx.x >> 5;
    int lane = threadIdx.x & 31;
    float* base = g_qkvb + (size_t)m * PROJ + wp * PH;

    const int segs[3] = {0, 64, 192};
    #pragma unroll
    for (int si = 0; si < 3; si++) {
        int seg = segs[si];
        float a  = base[seg + lane];
        float bb = base[seg + 32 + lane];
        float mx = warp_max_f32(fmaxf(a, bb));
        float ea = __expf(a - mx);
        float eb = __expf(bb - mx);
        float s2 = ea + eb;
        #pragma unroll
        for (int o = 16; o; o >>= 1) s2 += __shfl_xor_sync(0xffffffffu, s2, o);
        float inv = 1.0f / s2;
        base[seg + lane]      = ea * inv;
        base[seg + 32 + lane] = eb * inv;
    }
    if (lane < 2) {
        float v = base[320 + lane];
        base[320 + lane] = 1.0f / (1.0f + __expf(-v));
    }
}

// ============================================================
// Kernel 4: sequential scan v6 (kept from R11)
// ============================================================
__device__ __forceinline__ void ld16p(ull* dst, const float* __restrict__ src)
{
    const ulonglong2* p = reinterpret_cast<const ulonglong2*>(src);
    #pragma unroll
    for (int q = 0; q < 8; q++) {
        ulonglong2 v = p[q];
        dst[q * 2]     = v.x;
        dst[q * 2 + 1] = v.y;
    }
}

__device__ __forceinline__ float dot16p(const ull* a, const ull* b)
{
    ull s0 = 0ull, s1 = 0ull, s2 = 0ull, s3 = 0ull;
    #pragma unroll
    for (int j = 0; j < 16; j += 4) {
        s0 = fma_f32x2(a[j],     b[j],     s0);
        s1 = fma_f32x2(a[j + 1], b[j + 1], s1);
        s2 = fma_f32x2(a[j + 2], b[j + 2], s2);
        s3 = fma_f32x2(a[j + 3], b[j + 3], s3);
    }
    ull tt = add_f32x2(add_f32x2(s0, s1), add_f32x2(s2, s3));
    float lo, hi;
    unpack2(tt, lo, hi);
    return lo + hi;
}

__global__ void __launch_bounds__(128) scan_kernel()
{
    int bh = blockIdx.x;
    int b = bh >> 3, h = bh & 7;
    int t    = threadIdx.x;
    int i    = t >> 1;
    int c    = t & 1;
    int lane = t & 31;
    int w    = t >> 5;

    __shared__ __align__(16) float buf[2][PHP];
    __shared__ float h_sh[2][64];
    __shared__ __align__(16) float e_sh[4][64];

    ull W2[16], R2[16];
    #pragma unroll
    for (int j = 0; j < 16; j++) { W2[j] = 0ull; R2[j] = 0ull; }

    {
        const float* src = g_qkvb + (size_t)b * PROJ + h * PH;
        buf[0][t]       = src[t];
        buf[0][t + 128] = src[t + 128];
        if (t < PH - 256) buf[0][t + 256] = src[t + 256];
    }
    float p0, p1, p2 = 0.f;
    {
        const float* src = g_qkvb + (size_t)(BATCH + b) * PROJ + h * PH;
        p0 = src[t];
        p1 = src[t + 128];
        if (t < PH - 256) p2 = src[t + 256];
    }
    if (t < 64) { h_sh[0][t] = 0.f; h_sh[1][t] = 0.f; }
    __syncthreads();

    const int cofs = c * 32;

    for (int s = 0; s < S_LEN; s++) {
        {
            float* nb = buf[(s + 1) & 1];
            nb[t]       = p0;
            nb[t + 128] = p1;
            if (t < PH - 256) nb[t + 256] = p2;
        }
        if (s + 2 < S_LEN) {
            const float* src = g_qkvb + (size_t)((s + 2) * BATCH + b) * PROJ + h * PH;
            p0 = src[t];
            p1 = src[t + 128];
            if (t < PH - 256) p2 = src[t + 256];
        }

        const float* in = buf[s & 1];
        const float* hb = h_sh[s & 1];

        float h0 = hb[lane];
        float h1 = hb[lane + 32];
        float mx = warp_max_f32(fmaxf(h0, h1));
        float e0 = __expf(h0 - mx);
        float e1 = __expf(h1 - mx);
        e_sh[w][lane]      = e0;
        e_sh[w][lane + 32] = e1;
        float sm = e0 + e1;
        #pragma unroll
        for (int o = 16; o; o >>= 1) sm += __shfl_xor_sync(0xffffffffu, sm, o);
        float invTot = __fdividef(1.0f, sm);
        __syncwarp();

        ull k2[16];
        ld16p(k2, in + 64 + cofs);
        float vold = dot16p(W2, k2);
        vold += __shfl_xor_sync(0xffffffffu, vold, 1);
        float coef = in[320] * (in[128 + i] - vold);
        ull cd = pack_dup(coef);
        #pragma unroll
        for (int j = 0; j < 16; j++) W2[j] = fma_f32x2(cd, k2[j], W2[j]);

        ull q2[16];
        ld16p(q2, in + cofs);
        float z = dot16p(W2, q2);
        z += __shfl_xor_sync(0xffffffffu, z, 1);

        ull rk2[16];
        ld16p(rk2, in + 192 + cofs);
        float voldR = dot16p(R2, rk2);
        voldR += __shfl_xor_sync(0xffffffffu, voldR, 1);
        float coefR = in[321] * (in[256 + i] - voldR);
        ull crd = pack_dup(coefR);
        #pragma unroll
        for (int j = 0; j < 16; j++) R2[j] = fma_f32x2(crd, rk2[j], R2[j]);

        ull er2[16];
        ld16p(er2, &e_sh[w][cofs]);
        float hd = dot16p(R2, er2);
        hd += __shfl_xor_sync(0xffffffffu, hd, 1);
        float hn = z + hd * invTot;

        if (c == 0) {
            h_sh[(s + 1) & 1][i] = hn;
            uint32_t hi, lo;
            split_tf32(hn, hi, lo);
            size_t idx = (size_t)(s * BATCH + b) * OUTD + h * DHEAD + i;
            g_hs_hi[idx] = hi;
            g_hs_lo[idx] = lo;
        }
        __syncthreads();
    }
}

// ============================================================
// Launch
// ============================================================
extern "C" void kernel_launch(void* const* d_in, const int* in_sizes, int n_in,
                              void* d_out, int out_size)
{
    const float* x      = (const float*)d_in[0];
    const float* W_slow = (const float*)d_in[1];
    const float* W_out  = (const float*)d_in[2];
    const float* gamma  = (const float*)d_in[3];
    const float* betap  = (const float*)d_in[4];
    float* out = (float*)d_out;

    float*    p_qkvb = nullptr;
    uint32_t *p_nh = nullptr, *p_nl = nullptr, *p_hh = nullptr, *p_hl = nullptr;
    uint32_t *p_wsh = nullptr, *p_wsl = nullptr, *p_woh = nullptr, *p_wol = nullptr;
    cudaGetSymbolAddress((void**)&p_qkvb, g_qkvb);
    cudaGetSymbolAddress((void**)&p_nh,   g_normed_hi);
    cudaGetSymbolAddress((void**)&p_nl,   g_normed_lo);
    cudaGetSymbolAddress((void**)&p_hh,   g_hs_hi);
    cudaGetSymbolAddress((void**)&p_hl,   g_hs_lo);
    cudaGetSymbolAddress((void**)&p_wsh,  g_wslow_hi);
    cudaGetSymbolAddress((void**)&p_wsl,  g_wslow_lo);
    cudaGetSymbolAddress((void**)&p_woh,  g_wout_hi);
    cudaGetSymbolAddress((void**)&p_wol,  g_wout_lo);

    static bool attr_done = false;
    if (!attr_done) {
        cudaFuncSetAttribute((const void*)mma_gemm_nt<false>,
                             cudaFuncAttributeMaxDynamicSharedMemorySize,
                             GEMM_SMEM_BYTES);
        cudaFuncSetAttribute((const void*)mma_gemm_nt<true>,
                             cudaFuncAttributeMaxDynamicSharedMemorySize,
                             GEMM_SMEM_BYTES);
        attr_done = true;
    }

    // 0. split weights to tf32 hi/lo
    {
        int n1 = PROJ * INDIM;
        split_kernel<<<(n1 / 4 + 255) / 256, 256>>>(W_slow, p_wsh, p_wsl, n1);
        int n2 = INDIM * OUTD;
        split_kernel<<<(n2 / 4 + 255) / 256, 256>>>(W_out, p_woh, p_wol, n2);
    }

    // 1. LayerNorm -> tf32 hi/lo
    ln_kernel<<<MROWS, 256>>>(x, gamma, betap);

    // 2. qkvb = normed @ W_slow^T   (M=4096, N=2576, K=512)
    {
        dim3 grid((PROJ + TC_BN - 1) / TC_BN, MROWS / TC_BM);   // 21 x 32
        mma_gemm_nt<false><<<grid, 256, GEMM_SMEM_BYTES>>>(
            p_nh, p_nl, p_wsh, p_wsl, p_qkvb, nullptr, PROJ, INDIM);
    }

    // 3. softmax / sigmoid activations in place
    act_kernel<<<MROWS, 256>>>();

    // 4. sequential scan -> hs hi/lo
    scan_kernel<<<BATCH * HEADS, 128>>>();

    // 5. out = x + hs @ W_out^T     (M=4096, N=512, K=512)
    {
        dim3 grid(INDIM / TC_BN, MROWS / TC_BM);                // 4 x 32
        mma_gemm_nt<true><<<grid, 256, GEMM_SMEM_BYTES>>>(
            p_hh, p_hl, p_woh, p_wol, out, x, INDIM, OUTD);
    }
}

// round 13
// speedup vs baseline: 1.7332x; 1.2511x over previous
#include <cuda_runtime.h>
#include <cuda_bf16.h>
#include <cstdint>

#define S_LEN 512
#define BATCH 8
#define HEADS 8
#define DHEAD 64
#define INDIM 512
#define PH    322                 // 5*D + 2
#define PHP   324
#define PROJ  (HEADS * PH)        // 2576
#define MROWS (S_LEN * BATCH)     // 4096
#define OUTD  (HEADS * DHEAD)     // 512

typedef unsigned long long ull;

// ---- scratch (static device memory; no allocation at runtime) ----
__device__ float          g_qkvb[MROWS * PROJ];
__device__ __nv_bfloat16  g_normed_hi[MROWS * INDIM];
__device__ __nv_bfloat16  g_normed_lo[MROWS * INDIM];
__device__ __nv_bfloat16  g_hs_hi[MROWS * OUTD];
__device__ __nv_bfloat16  g_hs_lo[MROWS * OUTD];
__device__ __nv_bfloat16  g_wslow_hi[PROJ * INDIM];
__device__ __nv_bfloat16  g_wslow_lo[PROJ * INDIM];
__device__ __nv_bfloat16  g_wout_hi[INDIM * OUTD];
__device__ __nv_bfloat16  g_wout_lo[INDIM * OUTD];

// fp32 -> bf16 hi/lo split (both RN; A = hi + lo + O(2^-18 A))
__device__ __forceinline__ void split_bf16(float x, __nv_bfloat16& hi, __nv_bfloat16& lo)
{
    hi = __float2bfloat16_rn(x);
    lo = __float2bfloat16_rn(x - __bfloat162float(hi));
}

// m16n8k16 bf16 tensor-core MMA (full-rate; plain sm_103 OK)
__device__ __forceinline__ void mma_bf16(float* c, const uint32_t* a, const uint32_t* b)
{
    asm volatile(
        "mma.sync.aligned.m16n8k16.row.col.f32.bf16.bf16.f32 "
        "{%0,%1,%2,%3}, {%4,%5,%6,%7}, {%8,%9}, {%0,%1,%2,%3};"
        : "+f"(c[0]), "+f"(c[1]), "+f"(c[2]), "+f"(c[3])
        : "r"(a[0]), "r"(a[1]), "r"(a[2]), "r"(a[3]), "r"(b[0]), "r"(b[1]));
}

// ldmatrix x4 (sm_75+)
__device__ __forceinline__ void ldsm_x4(uint32_t* r, uint32_t addr)
{
    asm volatile("ldmatrix.sync.aligned.m8n8.x4.shared.b16 {%0,%1,%2,%3}, [%4];"
        : "=r"(r[0]), "=r"(r[1]), "=r"(r[2]), "=r"(r[3]) : "r"(addr));
}

// cp.async helpers
__device__ __forceinline__ uint32_t smem_u32(const void* p)
{
    uint32_t a;
    asm("{ .reg .u64 t; cvta.to.shared.u64 t, %1; cvt.u32.u64 %0, t; }"
        : "=r"(a) : "l"(p));
    return a;
}
__device__ __forceinline__ void cp_async16(uint32_t dst, const void* src, int src_bytes)
{
    asm volatile("cp.async.cg.shared.global [%0], [%1], 16, %2;"
                 :: "r"(dst), "l"(src), "r"(src_bytes) : "memory");
}
#define CP_COMMIT() asm volatile("cp.async.commit_group;" ::: "memory")
template<int N>
__device__ __forceinline__ void cp_wait()
{
    asm volatile("cp.async.wait_group %0;" :: "n"(N) : "memory");
}

// ---- packed f32x2 helpers (scan) ----
__device__ __forceinline__ ull fma_f32x2(ull a, ull b, ull c)
{
    ull d;
    asm("fma.rn.f32x2 %0, %1, %2, %3;" : "=l"(d) : "l"(a), "l"(b), "l"(c));
    return d;
}
__device__ __forceinline__ ull add_f32x2(ull a, ull b)
{
    ull d;
    asm("add.rn.f32x2 %0, %1, %2;" : "=l"(d) : "l"(a), "l"(b));
    return d;
}
__device__ __forceinline__ ull pack_dup(float x)
{
    ull d;
    asm("mov.b64 %0, {%1, %1};" : "=l"(d) : "f"(x));
    return d;
}
__device__ __forceinline__ void unpack2(ull v, float& lo, float& hi)
{
    asm("mov.b64 {%0, %1}, %2;" : "=f"(lo), "=f"(hi) : "l"(v));
}

// warp-wide float max via order-preserving int key + redux.sync.u32
__device__ __forceinline__ float warp_max_f32(float x)
{
    uint32_t b = __float_as_uint(x);
    uint32_t s = (uint32_t)((int32_t)b >> 31);
    uint32_t key = b ^ (s | 0x80000000u);
    uint32_t m;
    asm("redux.sync.max.u32 %0, %1, 0xffffffff;" : "=r"(m) : "r"(key));
    uint32_t mask = (m & 0x80000000u) ? 0x80000000u : 0xFFFFFFFFu;
    return __uint_as_float(m ^ mask);
}

// ============================================================
// Kernel 0: weight split (fp32 -> bf16 hi/lo); 8 elems/thread
// ============================================================
__global__ void __launch_bounds__(256) split_kernel(
    const float* __restrict__ src, __nv_bfloat16* __restrict__ dst_hi,
    __nv_bfloat16* __restrict__ dst_lo, int n)
{
    int idx = (blockIdx.x * 256 + threadIdx.x) * 8;
    if (idx < n) {
        float4 v0 = *reinterpret_cast<const float4*>(src + idx);
        float4 v1 = *reinterpret_cast<const float4*>(src + idx + 4);
        __nv_bfloat16 h[8], l[8];
        float xs[8] = {v0.x, v0.y, v0.z, v0.w, v1.x, v1.y, v1.z, v1.w};
        #pragma unroll
        for (int q = 0; q < 8; q++) split_bf16(xs[q], h[q], l[q]);
        *reinterpret_cast<uint4*>(dst_hi + idx) = *reinterpret_cast<uint4*>(h);
        *reinterpret_cast<uint4*>(dst_lo + idx) = *reinterpret_cast<uint4*>(l);
    }
}

// ============================================================
// Kernel 1: LayerNorm -> bf16 hi/lo
// ============================================================
__global__ void __launch_bounds__(256) ln_kernel(
    const float* __restrict__ x,
    const float* __restrict__ gamma,
    const float* __restrict__ beta)
{
    int m = blockIdx.x;
    int t = threadIdx.x;
    const float* row = x + (size_t)m * INDIM;
    float v0 = row[t];
    float v1 = row[t + 256];

    float s = v0 + v1;
    #pragma unroll
    for (int o = 16; o; o >>= 1) s += __shfl_xor_sync(0xffffffffu, s, o);

    __shared__ float red[8];
    __shared__ float red2[8];
    int w = t >> 5, lane = t & 31;
    if (lane == 0) red[w] = s;
    __syncthreads();
    float tot = 0.f;
    #pragma unroll
    for (int i = 0; i < 8; i++) tot += red[i];
    float mean = tot * (1.0f / INDIM);

    float d0 = v0 - mean, d1 = v1 - mean;
    float sq = d0 * d0 + d1 * d1;
    #pragma unroll
    for (int o = 16; o; o >>= 1) sq += __shfl_xor_sync(0xffffffffu, sq, o);
    if (lane == 0) red2[w] = sq;
    __syncthreads();
    float vtot = 0.f;
    #pragma unroll
    for (int i = 0; i < 8; i++) vtot += red2[i];
    float inv = rsqrtf(vtot * (1.0f / INDIM) + 1e-5f);

    float r0 = d0 * inv * gamma[t]       + beta[t];
    float r1 = d1 * inv * gamma[t + 256] + beta[t + 256];
    __nv_bfloat16 h0, l0, h1, l1;
    split_bf16(r0, h0, l0);
    split_bf16(r1, h1, l1);
    size_t base = (size_t)m * INDIM;
    g_normed_hi[base + t]       = h0;
    g_normed_lo[base + t]       = l0;
    g_normed_hi[base + t + 256] = h1;
    g_normed_lo[base + t + 256] = l1;
}

// ============================================================
// Kernel 2/5: BF16x3 GEMM, 4-stage cp.async, BK=16, ldmatrix
// C = A*B^T (+resid). A,B as bf16 hi/lo arrays.
// ============================================================
#define TC_BM 128
#define TC_BN 128
#define TC_BK 16
#define ROWW  12                          // words/row (48B for 32B payload; conflict-free)
#define STG_W   (TC_BM * ROWW)            // 1536 words per array
#define STAGE_W (4 * STG_W)               // 6144 words per stage
#define NSTAGE  4
#define GEMM_SMEM_BYTES (NSTAGE * STAGE_W * 4)   // 98304

template<bool RESID>
__global__ void __launch_bounds__(256, 2) mma_gemm_nt(
    const __nv_bfloat16* __restrict__ Ahg, const __nv_bfloat16* __restrict__ Alg,
    const __nv_bfloat16* __restrict__ Bhg, const __nv_bfloat16* __restrict__ Blg,
    float* __restrict__ C,
    const float* __restrict__ resid,
    int Ndim, int Kdim)
{
    extern __shared__ uint32_t sm[];

    const int tid    = threadIdx.x;
    const int lane   = tid & 31;
    const int wid    = tid >> 5;
    const int warp_m = wid & 3;
    const int warp_n = wid >> 2;
    const int g      = lane >> 2;
    const int tq     = lane & 3;
    const int mBase  = blockIdx.y * TC_BM;
    const int nBase  = blockIdx.x * TC_BN;

    const int lrow = tid >> 1;            // 0..127
    const int lce  = (tid & 1) * 8;       // bf16 element offset (0 or 8)
    const uint32_t smBase = smem_u32(sm);

    float c[2][8][4];
    #pragma unroll
    for (int am = 0; am < 2; am++)
        #pragma unroll
        for (int an = 0; an < 8; an++)
            #pragma unroll
            for (int q = 0; q < 4; q++) c[am][an][q] = 0.f;

    const int NKB = Kdim / TC_BK;         // 32

    const int  nrow  = nBase + lrow;
    const int  nb    = (nrow < Ndim) ? 16 : 0;
    const size_t aRow = (size_t)(mBase + lrow) * Kdim + lce;
    const size_t bRow = (size_t)((nrow < Ndim) ? nrow : 0) * Kdim + lce;
    const uint32_t doff = (uint32_t)(lrow * ROWW * 4 + (tid & 1) * 16);

    auto issue_stage = [&](int kb, int st) {
        const int ko = kb * TC_BK;
        const uint32_t stB = smBase + (uint32_t)(st * STAGE_W) * 4u + doff;
        cp_async16(stB,                                Ahg + aRow + ko, 16);
        cp_async16(stB + (uint32_t)STG_W * 4u,         Alg + aRow + ko, 16);
        cp_async16(stB + (uint32_t)(2 * STG_W) * 4u,   Bhg + bRow + ko, nb);
        cp_async16(stB + (uint32_t)(3 * STG_W) * 4u,   Blg + bRow + ko, nb);
        CP_COMMIT();
    };

    issue_stage(0, 0);
    issue_stage(1, 1);
    issue_stage(2, 2);

    // ---- per-lane ldmatrix addresses (byte offsets within a stage) ----
    const int mm = lane >> 3;   // matrix index 0..3
    const int mr = lane & 7;    // row within matrix
    // A x4: (m0-7,k0-7),(m8-15,k0-7),(m0-7,k8-15),(m8-15,k8-15)
    uint32_t offA[2];
    #pragma unroll
    for (int am = 0; am < 2; am++) {
        int mrow = warp_m * 32 + am * 16 + (mm & 1) * 8 + mr;
        offA[am] = (uint32_t)(mrow * ROWW * 4 + (mm >> 1) * 16);
    }
    // B x4 for pair p: (tile2p,k0-7),(tile2p,k8-15),(tile2p+1,k0-7),(tile2p+1,k8-15)
    uint32_t offB[4];
    #pragma unroll
    for (int p = 0; p < 4; p++) {
        int nr = warp_n * 64 + (2 * p + (mm >> 1)) * 8 + mr;
        offB[p] = (uint32_t)(nr * ROWW * 4 + (mm & 1) * 16) + (uint32_t)(2 * STG_W) * 4u;
    }

    for (int kb = 0; kb < NKB; kb++) {
        cp_wait<2>();
        __syncthreads();

        const uint32_t stB = smBase + (uint32_t)((kb & 3) * STAGE_W) * 4u;
        const uint32_t loOff = (uint32_t)STG_W * 4u;

        uint32_t ah[2][4], al[2][4];
        #pragma unroll
        for (int am = 0; am < 2; am++) {
            ldsm_x4(ah[am], stB + offA[am]);
            ldsm_x4(al[am], stB + offA[am] + loOff);
        }
        uint32_t bh[8][2], bl[8][2];
        #pragma unroll
        for (int p = 0; p < 4; p++) {
            uint32_t rh[4], rl[4];
            ldsm_x4(rh, stB + offB[p]);
            ldsm_x4(rl, stB + offB[p] + loOff);
            bh[2 * p][0] = rh[0]; bh[2 * p][1] = rh[1];
            bh[2 * p + 1][0] = rh[2]; bh[2 * p + 1][1] = rh[3];
            bl[2 * p][0] = rl[0]; bl[2 * p][1] = rl[1];
            bl[2 * p + 1][0] = rl[2]; bl[2 * p + 1][1] = rl[3];
        }

        #pragma unroll
        for (int an = 0; an < 8; an++)
            #pragma unroll
            for (int am = 0; am < 2; am++) {
                mma_bf16(c[am][an], ah[am], bh[an]);
                mma_bf16(c[am][an], al[am], bh[an]);
                mma_bf16(c[am][an], ah[am], bl[an]);
            }

        if (kb + 3 < NKB) issue_stage(kb + 3, (kb + 3) & 3);
    }

    #pragma unroll
    for (int am = 0; am < 2; am++) {
        int r0 = mBase + warp_m * 32 + am * 16 + g;
        #pragma unroll
        for (int an = 0; an < 8; an++) {
            int col = nBase + warp_n * 64 + an * 8 + 2 * tq;
            if (col < Ndim) {
                float2 v0 = make_float2(c[am][an][0], c[am][an][1]);
                float2 v1 = make_float2(c[am][an][2], c[am][an][3]);
                if (RESID) {
                    float2 q0 = *reinterpret_cast<const float2*>(
                        resid + (size_t)r0 * Ndim + col);
                    float2 q1 = *reinterpret_cast<const float2*>(
                        resid + (size_t)(r0 + 8) * Ndim + col);
                    v0.x += q0.x; v0.y += q0.y;
                    v1.x += q1.x; v1.y += q1.y;
                }
                *reinterpret_cast<float2*>(C + (size_t)r0 * Ndim + col) = v0;
                *reinterpret_cast<float2*>(C + (size_t)(r0 + 8) * Ndim + col) = v1;
            }
        }
    }
}

// ============================================================
// Kernel 3: per-head activations in place on g_qkvb
// ============================================================
__global__ void __launch_bounds__(256) act_kernel()
{
    int m    = blockIdx.x;
    int wp   = threadIdx.x >> 5;
    int lane = threadIdx.x & 31;
    float* base = g_qkvb + (size_t)m * PROJ + wp * PH;

    const int segs[3] = {0, 64, 192};
    #pragma unroll
    for (int si = 0; si < 3; si++) {
        int seg = segs[si];
        float a  = base[seg + lane];
        float bb = base[seg + 32 + lane];
        float mx = warp_max_f32(fmaxf(a, bb));
        float ea = __expf(a - mx);
        float eb = __expf(bb - mx);
        float s2 = ea + eb;
        #pragma unroll
        for (int o = 16; o; o >>= 1) s2 += __shfl_xor_sync(0xffffffffu, s2, o);
        float inv = 1.0f / s2;
        base[seg + lane]      = ea * inv;
        base[seg + 32 + lane] = eb * inv;
    }
    if (lane < 2) {
        float v = base[320 + lane];
        base[320 + lane] = 1.0f / (1.0f + __expf(-v));
    }
}

// ============================================================
// Kernel 4: sequential scan v6 (from R11/12) -> hs bf16 hi/lo
// ============================================================
__device__ __forceinline__ void ld16p(ull* dst, const float* __restrict__ src)
{
    const ulonglong2* p = reinterpret_cast<const ulonglong2*>(src);
    #pragma unroll
    for (int q = 0; q < 8; q++) {
        ulonglong2 v = p[q];
        dst[q * 2]     = v.x;
        dst[q * 2 + 1] = v.y;
    }
}

__device__ __forceinline__ float dot16p(const ull* a, const ull* b)
{
    ull s0 = 0ull, s1 = 0ull, s2 = 0ull, s3 = 0ull;
    #pragma unroll
    for (int j = 0; j < 16; j += 4) {
        s0 = fma_f32x2(a[j],     b[j],     s0);
        s1 = fma_f32x2(a[j + 1], b[j + 1], s1);
        s2 = fma_f32x2(a[j + 2], b[j + 2], s2);
        s3 = fma_f32x2(a[j + 3], b[j + 3], s3);
    }
    ull tt = add_f32x2(add_f32x2(s0, s1), add_f32x2(s2, s3));
    float lo, hi;
    unpack2(tt, lo, hi);
    return lo + hi;
}

__global__ void __launch_bounds__(128) scan_kernel()
{
    int bh = blockIdx.x;
    int b = bh >> 3, h = bh & 7;
    int t    = threadIdx.x;
    int i    = t >> 1;
    int c    = t & 1;
    int lane = t & 31;
    int w    = t >> 5;

    __shared__ __align__(16) float buf[2][PHP];
    __shared__ float h_sh[2][64];
    __shared__ __align__(16) float e_sh[4][64];

    ull W2[16], R2[16];
    #pragma unroll
    for (int j = 0; j < 16; j++) { W2[j] = 0ull; R2[j] = 0ull; }

    {
        const float* src = g_qkvb + (size_t)b * PROJ + h * PH;
        buf[0][t]       = src[t];
        buf[0][t + 128] = src[t + 128];
        if (t < PH - 256) buf[0][t + 256] = src[t + 256];
    }
    float p0, p1, p2 = 0.f;
    {
        const float* src = g_qkvb + (size_t)(BATCH + b) * PROJ + h * PH;
        p0 = src[t];
        p1 = src[t + 128];
        if (t < PH - 256) p2 = src[t + 256];
    }
    if (t < 64) { h_sh[0][t] = 0.f; h_sh[1][t] = 0.f; }
    __syncthreads();

    const int cofs = c * 32;

    for (int s = 0; s < S_LEN; s++) {
        {
            float* nb = buf[(s + 1) & 1];
            nb[t]       = p0;
            nb[t + 128] = p1;
            if (t < PH - 256) nb[t + 256] = p2;
        }
        if (s + 2 < S_LEN) {
            const float* src = g_qkvb + (size_t)((s + 2) * BATCH + b) * PROJ + h * PH;
            p0 = src[t];
            p1 = src[t + 128];
            if (t < PH - 256) p2 = src[t + 256];
        }

        const float* in = buf[s & 1];
        const float* hb = h_sh[s & 1];

        float h0 = hb[lane];
        float h1 = hb[lane + 32];
        float mx = warp_max_f32(fmaxf(h0, h1));
        float e0 = __expf(h0 - mx);
        float e1 = __expf(h1 - mx);
        e_sh[w][lane]      = e0;
        e_sh[w][lane + 32] = e1;
        float sm = e0 + e1;
        #pragma unroll
        for (int o = 16; o; o >>= 1) sm += __shfl_xor_sync(0xffffffffu, sm, o);
        float invTot = __fdividef(1.0f, sm);
        __syncwarp();

        ull k2[16];
        ld16p(k2, in + 64 + cofs);
        float vold = dot16p(W2, k2);
        vold += __shfl_xor_sync(0xffffffffu, vold, 1);
        float coef = in[320] * (in[128 + i] - vold);
        ull cd = pack_dup(coef);
        #pragma unroll
        for (int j = 0; j < 16; j++) W2[j] = fma_f32x2(cd, k2[j], W2[j]);

        ull q2[16];
        ld16p(q2, in + cofs);
        float z = dot16p(W2, q2);
        z += __shfl_xor_sync(0xffffffffu, z, 1);

        ull rk2[16];
        ld16p(rk2, in + 192 + cofs);
        float voldR = dot16p(R2, rk2);
        voldR += __shfl_xor_sync(0xffffffffu, voldR, 1);
        float coefR = in[321] * (in[256 + i] - voldR);
        ull crd = pack_dup(coefR);
        #pragma unroll
        for (int j = 0; j < 16; j++) R2[j] = fma_f32x2(crd, rk2[j], R2[j]);

        ull er2[16];
        ld16p(er2, &e_sh[w][cofs]);
        float hd = dot16p(R2, er2);
        hd += __shfl_xor_sync(0xffffffffu, hd, 1);
        float hn = z + hd * invTot;

        if (c == 0) {
            h_sh[(s + 1) & 1][i] = hn;
            __nv_bfloat16 hi, lo;
            split_bf16(hn, hi, lo);
            size_t idx = (size_t)(s * BATCH + b) * OUTD + h * DHEAD + i;
            g_hs_hi[idx] = hi;
            g_hs_lo[idx] = lo;
        }
        __syncthreads();
    }
}

// ============================================================
// Launch
// ============================================================
extern "C" void kernel_launch(void* const* d_in, const int* in_sizes, int n_in,
                              void* d_out, int out_size)
{
    const float* x      = (const float*)d_in[0];
    const float* W_slow = (const float*)d_in[1];
    const float* W_out  = (const float*)d_in[2];
    const float* gamma  = (const float*)d_in[3];
    const float* betap  = (const float*)d_in[4];
    float* out = (float*)d_out;

    float* p_qkvb = nullptr;
    __nv_bfloat16 *p_nh = nullptr, *p_nl = nullptr, *p_hh = nullptr, *p_hl = nullptr;
    __nv_bfloat16 *p_wsh = nullptr, *p_wsl = nullptr, *p_woh = nullptr, *p_wol = nullptr;
    cudaGetSymbolAddress((void**)&p_qkvb, g_qkvb);
    cudaGetSymbolAddress((void**)&p_nh,   g_normed_hi);
    cudaGetSymbolAddress((void**)&p_nl,   g_normed_lo);
    cudaGetSymbolAddress((void**)&p_hh,   g_hs_hi);
    cudaGetSymbolAddress((void**)&p_hl,   g_hs_lo);
    cudaGetSymbolAddress((void**)&p_wsh,  g_wslow_hi);
    cudaGetSymbolAddress((void**)&p_wsl,  g_wslow_lo);
    cudaGetSymbolAddress((void**)&p_woh,  g_wout_hi);
    cudaGetSymbolAddress((void**)&p_wol,  g_wout_lo);

    static bool attr_done = false;
    if (!attr_done) {
        cudaFuncSetAttribute((const void*)mma_gemm_nt<false>,
                             cudaFuncAttributeMaxDynamicSharedMemorySize,
                             GEMM_SMEM_BYTES);
        cudaFuncSetAttribute((const void*)mma_gemm_nt<true>,
                             cudaFuncAttributeMaxDynamicSharedMemorySize,
                             GEMM_SMEM_BYTES);
        attr_done = true;
    }

    // 0. split weights to bf16 hi/lo
    {
        int n1 = PROJ * INDIM;
        split_kernel<<<(n1 / 8 + 255) / 256, 256>>>(W_slow, p_wsh, p_wsl, n1);
        int n2 = INDIM * OUTD;
        split_kernel<<<(n2 / 8 + 255) / 256, 256>>>(W_out, p_woh, p_wol, n2);
    }

    // 1. LayerNorm -> bf16 hi/lo
    ln_kernel<<<MROWS, 256>>>(x, gamma, betap);

    // 2. qkvb = normed @ W_slow^T   (M=4096, N=2576, K=512)
    {
        dim3 grid((PROJ + TC_BN - 1) / TC_BN, MROWS / TC_BM);   // 21 x 32
        mma_gemm_nt<false><<<grid, 256, GEMM_SMEM_BYTES>>>(
            p_nh, p_nl, p_wsh, p_wsl, p_qkvb, nullptr, PROJ, INDIM);
    }

    // 3. softmax / sigmoid activations in place
    act_kernel<<<MROWS, 256>>>();

    // 4. sequential scan -> hs bf16 hi/lo
    scan_kernel<<<BATCH * HEADS, 128>>>();

    // 5. out = x + hs @ W_out^T     (M=4096, N=512, K=512)
    {
        dim3 grid(INDIM / TC_BN, MROWS / TC_BM);                // 4 x 32
        mma_gemm_nt<true><<<grid, 256, GEMM_SMEM_BYTES>>>(
            p_hh, p_hl, p_woh, p_wol, out, x, INDIM, OUTD);
    }
}

// round 14
// speedup vs baseline: 1.8218x; 1.0511x over previous
#include <cuda_runtime.h>
#include <cuda_bf16.h>
#include <cstdint>

#define S_LEN 512
#define BATCH 8
#define HEADS 8
#define DHEAD 64
#define INDIM 512
#define PH    322                 // 5*D + 2
#define PHP   324
#define PROJ  (HEADS * PH)        // 2576
#define MROWS (S_LEN * BATCH)     // 4096
#define OUTD  (HEADS * DHEAD)     // 512

#define NCHUNK 4
#define CS     (S_LEN / NCHUNK)   // 128 steps per chunk
#define MCHUNK (CS * BATCH)       // 1024 rows per chunk

typedef unsigned long long ull;

// ---- scratch (static device memory; no allocation at runtime) ----
__device__ float          g_qkvb[MROWS * PROJ];
__device__ __nv_bfloat16  g_normed_hi[MROWS * INDIM];
__device__ __nv_bfloat16  g_normed_lo[MROWS * INDIM];
__device__ __nv_bfloat16  g_hs_hi[MROWS * OUTD];
__device__ __nv_bfloat16  g_hs_lo[MROWS * OUTD];
__device__ __nv_bfloat16  g_wslow_hi[PROJ * INDIM];
__device__ __nv_bfloat16  g_wslow_lo[PROJ * INDIM];
__device__ __nv_bfloat16  g_wout_hi[INDIM * OUTD];
__device__ __nv_bfloat16  g_wout_lo[INDIM * OUTD];
// scan state across chunks
__device__ ull   g_Wst[64 * 128 * 16];
__device__ ull   g_Rst[64 * 128 * 16];
__device__ float g_hst[64 * 64];

// fp32 -> bf16 hi/lo split
__device__ __forceinline__ void split_bf16(float x, __nv_bfloat16& hi, __nv_bfloat16& lo)
{
    hi = __float2bfloat16_rn(x);
    lo = __float2bfloat16_rn(x - __bfloat162float(hi));
}

// m16n8k16 bf16 tensor-core MMA
__device__ __forceinline__ void mma_bf16(float* c, const uint32_t* a, const uint32_t* b)
{
    asm volatile(
        "mma.sync.aligned.m16n8k16.row.col.f32.bf16.bf16.f32 "
        "{%0,%1,%2,%3}, {%4,%5,%6,%7}, {%8,%9}, {%0,%1,%2,%3};"
        : "+f"(c[0]), "+f"(c[1]), "+f"(c[2]), "+f"(c[3])
        : "r"(a[0]), "r"(a[1]), "r"(a[2]), "r"(a[3]), "r"(b[0]), "r"(b[1]));
}

__device__ __forceinline__ void ldsm_x4(uint32_t* r, uint32_t addr)
{
    asm volatile("ldmatrix.sync.aligned.m8n8.x4.shared.b16 {%0,%1,%2,%3}, [%4];"
        : "=r"(r[0]), "=r"(r[1]), "=r"(r[2]), "=r"(r[3]) : "r"(addr));
}

__device__ __forceinline__ uint32_t smem_u32(const void* p)
{
    uint32_t a;
    asm("{ .reg .u64 t; cvta.to.shared.u64 t, %1; cvt.u32.u64 %0, t; }"
        : "=r"(a) : "l"(p));
    return a;
}
__device__ __forceinline__ void cp_async16(uint32_t dst, const void* src, int src_bytes)
{
    asm volatile("cp.async.cg.shared.global [%0], [%1], 16, %2;"
                 :: "r"(dst), "l"(src), "r"(src_bytes) : "memory");
}
#define CP_COMMIT() asm volatile("cp.async.commit_group;" ::: "memory")
template<int N>
__device__ __forceinline__ void cp_wait()
{
    asm volatile("cp.async.wait_group %0;" :: "n"(N) : "memory");
}

// ---- packed f32x2 helpers (scan) ----
__device__ __forceinline__ ull fma_f32x2(ull a, ull b, ull c)
{
    ull d;
    asm("fma.rn.f32x2 %0, %1, %2, %3;" : "=l"(d) : "l"(a), "l"(b), "l"(c));
    return d;
}
__device__ __forceinline__ ull add_f32x2(ull a, ull b)
{
    ull d;
    asm("add.rn.f32x2 %0, %1, %2;" : "=l"(d) : "l"(a), "l"(b));
    return d;
}
__device__ __forceinline__ ull pack_dup(float x)
{
    ull d;
    asm("mov.b64 %0, {%1, %1};" : "=l"(d) : "f"(x));
    return d;
}
__device__ __forceinline__ void unpack2(ull v, float& lo, float& hi)
{
    asm("mov.b64 {%0, %1}, %2;" : "=f"(lo), "=f"(hi) : "l"(v));
}

__device__ __forceinline__ float warp_max_f32(float x)
{
    uint32_t b = __float_as_uint(x);
    uint32_t s = (uint32_t)((int32_t)b >> 31);
    uint32_t key = b ^ (s | 0x80000000u);
    uint32_t m;
    asm("redux.sync.max.u32 %0, %1, 0xffffffff;" : "=r"(m) : "r"(key));
    uint32_t mask = (m & 0x80000000u) ? 0x80000000u : 0xFFFFFFFFu;
    return __uint_as_float(m ^ mask);
}

// ============================================================
// Kernel 0: weight split
// ============================================================
__global__ void __launch_bounds__(256) split_kernel(
    const float* __restrict__ src, __nv_bfloat16* __restrict__ dst_hi,
    __nv_bfloat16* __restrict__ dst_lo, int n)
{
    int idx = (blockIdx.x * 256 + threadIdx.x) * 8;
    if (idx < n) {
        float4 v0 = *reinterpret_cast<const float4*>(src + idx);
        float4 v1 = *reinterpret_cast<const float4*>(src + idx + 4);
        __nv_bfloat16 h[8], l[8];
        float xs[8] = {v0.x, v0.y, v0.z, v0.w, v1.x, v1.y, v1.z, v1.w};
        #pragma unroll
        for (int q = 0; q < 8; q++) split_bf16(xs[q], h[q], l[q]);
        *reinterpret_cast<uint4*>(dst_hi + idx) = *reinterpret_cast<uint4*>(h);
        *reinterpret_cast<uint4*>(dst_lo + idx) = *reinterpret_cast<uint4*>(l);
    }
}

// ============================================================
// Kernel 1: LayerNorm -> bf16 hi/lo
// ============================================================
__global__ void __launch_bounds__(256) ln_kernel(
    const float* __restrict__ x,
    const float* __restrict__ gamma,
    const float* __restrict__ beta)
{
    int m = blockIdx.x;
    int t = threadIdx.x;
    const float* row = x + (size_t)m * INDIM;
    float v0 = row[t];
    float v1 = row[t + 256];

    float s = v0 + v1;
    #pragma unroll
    for (int o = 16; o; o >>= 1) s += __shfl_xor_sync(0xffffffffu, s, o);

    __shared__ float red[8];
    __shared__ float red2[8];
    int w = t >> 5, lane = t & 31;
    if (lane == 0) red[w] = s;
    __syncthreads();
    float tot = 0.f;
    #pragma unroll
    for (int i = 0; i < 8; i++) tot += red[i];
    float mean = tot * (1.0f / INDIM);

    float d0 = v0 - mean, d1 = v1 - mean;
    float sq = d0 * d0 + d1 * d1;
    #pragma unroll
    for (int o = 16; o; o >>= 1) sq += __shfl_xor_sync(0xffffffffu, sq, o);
    if (lane == 0) red2[w] = sq;
    __syncthreads();
    float vtot = 0.f;
    #pragma unroll
    for (int i = 0; i < 8; i++) vtot += red2[i];
    float inv = rsqrtf(vtot * (1.0f / INDIM) + 1e-5f);

    float r0 = d0 * inv * gamma[t]       + beta[t];
    float r1 = d1 * inv * gamma[t + 256] + beta[t + 256];
    __nv_bfloat16 h0, l0, h1, l1;
    split_bf16(r0, h0, l0);
    split_bf16(r1, h1, l1);
    size_t base = (size_t)m * INDIM;
    g_normed_hi[base + t]       = h0;
    g_normed_lo[base + t]       = l0;
    g_normed_hi[base + t + 256] = h1;
    g_normed_lo[base + t + 256] = l1;
}

// ============================================================
// Kernel 2/5: BF16x3 GEMM, 4-stage cp.async, BK=16, ldmatrix
// m_off: row offset for chunked launches.
// ============================================================
#define TC_BM 128
#define TC_BN 128
#define TC_BK 16
#define ROWW  12
#define STG_W   (TC_BM * ROWW)
#define STAGE_W (4 * STG_W)
#define NSTAGE  4
#define GEMM_SMEM_BYTES (NSTAGE * STAGE_W * 4)

template<bool RESID>
__global__ void __launch_bounds__(256, 2) mma_gemm_nt(
    const __nv_bfloat16* __restrict__ Ahg, const __nv_bfloat16* __restrict__ Alg,
    const __nv_bfloat16* __restrict__ Bhg, const __nv_bfloat16* __restrict__ Blg,
    float* __restrict__ C,
    const float* __restrict__ resid,
    int Ndim, int Kdim, int m_off)
{
    extern __shared__ uint32_t sm[];

    const int tid    = threadIdx.x;
    const int lane   = tid & 31;
    const int wid    = tid >> 5;
    const int warp_m = wid & 3;
    const int warp_n = wid >> 2;
    const int g      = lane >> 2;
    const int tq     = lane & 3;
    const int mBase  = blockIdx.y * TC_BM + m_off;
    const int nBase  = blockIdx.x * TC_BN;

    const int lrow = tid >> 1;
    const int lce  = (tid & 1) * 8;
    const uint32_t smBase = smem_u32(sm);

    float c[2][8][4];
    #pragma unroll
    for (int am = 0; am < 2; am++)
        #pragma unroll
        for (int an = 0; an < 8; an++)
            #pragma unroll
            for (int q = 0; q < 4; q++) c[am][an][q] = 0.f;

    const int NKB = Kdim / TC_BK;

    const int  nrow  = nBase + lrow;
    const int  nb    = (nrow < Ndim) ? 16 : 0;
    const size_t aRow = (size_t)(mBase + lrow) * Kdim + lce;
    const size_t bRow = (size_t)((nrow < Ndim) ? nrow : 0) * Kdim + lce;
    const uint32_t doff = (uint32_t)(lrow * ROWW * 4 + (tid & 1) * 16);

    auto issue_stage = [&](int kb, int st) {
        const int ko = kb * TC_BK;
        const uint32_t stB = smBase + (uint32_t)(st * STAGE_W) * 4u + doff;
        cp_async16(stB,                                Ahg + aRow + ko, 16);
        cp_async16(stB + (uint32_t)STG_W * 4u,         Alg + aRow + ko, 16);
        cp_async16(stB + (uint32_t)(2 * STG_W) * 4u,   Bhg + bRow + ko, nb);
        cp_async16(stB + (uint32_t)(3 * STG_W) * 4u,   Blg + bRow + ko, nb);
        CP_COMMIT();
    };

    issue_stage(0, 0);
    issue_stage(1, 1);
    issue_stage(2, 2);

    const int mm = lane >> 3;
    const int mr = lane & 7;
    uint32_t offA[2];
    #pragma unroll
    for (int am = 0; am < 2; am++) {
        int mrow = warp_m * 32 + am * 16 + (mm & 1) * 8 + mr;
        offA[am] = (uint32_t)(mrow * ROWW * 4 + (mm >> 1) * 16);
    }
    uint32_t offB[4];
    #pragma unroll
    for (int p = 0; p < 4; p++) {
        int nr = warp_n * 64 + (2 * p + (mm >> 1)) * 8 + mr;
        offB[p] = (uint32_t)(nr * ROWW * 4 + (mm & 1) * 16) + (uint32_t)(2 * STG_W) * 4u;
    }

    for (int kb = 0; kb < NKB; kb++) {
        cp_wait<2>();
        __syncthreads();

        const uint32_t stB = smBase + (uint32_t)((kb & 3) * STAGE_W) * 4u;
        const uint32_t loOff = (uint32_t)STG_W * 4u;

        uint32_t ah[2][4], al[2][4];
        #pragma unroll
        for (int am = 0; am < 2; am++) {
            ldsm_x4(ah[am], stB + offA[am]);
            ldsm_x4(al[am], stB + offA[am] + loOff);
        }
        uint32_t bh[8][2], bl[8][2];
        #pragma unroll
        for (int p = 0; p < 4; p++) {
            uint32_t rh[4], rl[4];
            ldsm_x4(rh, stB + offB[p]);
            ldsm_x4(rl, stB + offB[p] + loOff);
            bh[2 * p][0] = rh[0]; bh[2 * p][1] = rh[1];
            bh[2 * p + 1][0] = rh[2]; bh[2 * p + 1][1] = rh[3];
            bl[2 * p][0] = rl[0]; bl[2 * p][1] = rl[1];
            bl[2 * p + 1][0] = rl[2]; bl[2 * p + 1][1] = rl[3];
        }

        #pragma unroll
        for (int an = 0; an < 8; an++)
            #pragma unroll
            for (int am = 0; am < 2; am++) {
                mma_bf16(c[am][an], ah[am], bh[an]);
                mma_bf16(c[am][an], al[am], bh[an]);
                mma_bf16(c[am][an], ah[am], bl[an]);
            }

        if (kb + 3 < NKB) issue_stage(kb + 3, (kb + 3) & 3);
    }

    #pragma unroll
    for (int am = 0; am < 2; am++) {
        int r0 = mBase + warp_m * 32 + am * 16 + g;
        #pragma unroll
        for (int an = 0; an < 8; an++) {
            int col = nBase + warp_n * 64 + an * 8 + 2 * tq;
            if (col < Ndim) {
                float2 v0 = make_float2(c[am][an][0], c[am][an][1]);
                float2 v1 = make_float2(c[am][an][2], c[am][an][3]);
                if (RESID) {
                    float2 q0 = *reinterpret_cast<const float2*>(
                        resid + (size_t)r0 * Ndim + col);
                    float2 q1 = *reinterpret_cast<const float2*>(
                        resid + (size_t)(r0 + 8) * Ndim + col);
                    v0.x += q0.x; v0.y += q0.y;
                    v1.x += q1.x; v1.y += q1.y;
                }
                *reinterpret_cast<float2*>(C + (size_t)r0 * Ndim + col) = v0;
                *reinterpret_cast<float2*>(C + (size_t)(r0 + 8) * Ndim + col) = v1;
            }
        }
    }
}

// ============================================================
// Kernel 3: per-head activations (chunked via m_off)
// ============================================================
__global__ void __launch_bounds__(256) act_kernel(int m_off)
{
    int m    = blockIdx.x + m_off;
    int wp   = threadIdx.x >> 5;
    int lane = threadIdx.x & 31;
    float* base = g_qkvb + (size_t)m * PROJ + wp * PH;

    const int segs[3] = {0, 64, 192};
    #pragma unroll
    for (int si = 0; si < 3; si++) {
        int seg = segs[si];
        float a  = base[seg + lane];
        float bb = base[seg + 32 + lane];
        float mx = warp_max_f32(fmaxf(a, bb));
        float ea = __expf(a - mx);
        float eb = __expf(bb - mx);
        float s2 = ea + eb;
        #pragma unroll
        for (int o = 16; o; o >>= 1) s2 += __shfl_xor_sync(0xffffffffu, s2, o);
        float inv = 1.0f / s2;
        base[seg + lane]      = ea * inv;
        base[seg + 32 + lane] = eb * inv;
    }
    if (lane < 2) {
        float v = base[320 + lane];
        base[320 + lane] = 1.0f / (1.0f + __expf(-v));
    }
}

// ============================================================
// Kernel 4: scan chunk [s0, s0+CS). State persisted in g_Wst/g_Rst/g_hst.
// ============================================================
__device__ __forceinline__ void ld16p(ull* dst, const float* __restrict__ src)
{
    const ulonglong2* p = reinterpret_cast<const ulonglong2*>(src);
    #pragma unroll
    for (int q = 0; q < 8; q++) {
        ulonglong2 v = p[q];
        dst[q * 2]     = v.x;
        dst[q * 2 + 1] = v.y;
    }
}

__device__ __forceinline__ float dot16p(const ull* a, const ull* b)
{
    ull s0 = 0ull, s1 = 0ull, s2 = 0ull, s3 = 0ull;
    #pragma unroll
    for (int j = 0; j < 16; j += 4) {
        s0 = fma_f32x2(a[j],     b[j],     s0);
        s1 = fma_f32x2(a[j + 1], b[j + 1], s1);
        s2 = fma_f32x2(a[j + 2], b[j + 2], s2);
        s3 = fma_f32x2(a[j + 3], b[j + 3], s3);
    }
    ull tt = add_f32x2(add_f32x2(s0, s1), add_f32x2(s2, s3));
    float lo, hi;
    unpack2(tt, lo, hi);
    return lo + hi;
}

__global__ void __launch_bounds__(128) scan_kernel(int s0, int doInit)
{
    int bh = blockIdx.x;
    int b = bh >> 3, h = bh & 7;
    int t    = threadIdx.x;
    int i    = t >> 1;
    int c    = t & 1;
    int lane = t & 31;
    int w    = t >> 5;

    __shared__ __align__(16) float buf[2][PHP];
    __shared__ float h_sh[2][64];
    __shared__ __align__(16) float e_sh[4][64];

    ull W2[16], R2[16];
    if (doInit) {
        #pragma unroll
        for (int j = 0; j < 16; j++) { W2[j] = 0ull; R2[j] = 0ull; }
        if (t < 64) h_sh[0][t] = 0.f;
    } else {
        const ull* ws = g_Wst + ((size_t)bh * 128 + t) * 16;
        const ull* rs = g_Rst + ((size_t)bh * 128 + t) * 16;
        #pragma unroll
        for (int j = 0; j < 16; j++) { W2[j] = ws[j]; R2[j] = rs[j]; }
        if (t < 64) h_sh[0][t] = g_hst[bh * 64 + t];
    }

    {
        const float* src = g_qkvb + (size_t)(s0 * BATCH + b) * PROJ + h * PH;
        buf[0][t]       = src[t];
        buf[0][t + 128] = src[t + 128];
        if (t < PH - 256) buf[0][t + 256] = src[t + 256];
    }
    float p0, p1, p2 = 0.f;
    {
        const float* src = g_qkvb + (size_t)((s0 + 1) * BATCH + b) * PROJ + h * PH;
        p0 = src[t];
        p1 = src[t + 128];
        if (t < PH - 256) p2 = src[t + 256];
    }
    __syncthreads();

    const int cofs = c * 32;

    for (int ls = 0; ls < CS; ls++) {
        const int s = s0 + ls;
        {
            float* nb = buf[(ls + 1) & 1];
            nb[t]       = p0;
            nb[t + 128] = p1;
            if (t < PH - 256) nb[t + 256] = p2;
        }
        if (s + 2 < S_LEN) {
            const float* src = g_qkvb + (size_t)((s + 2) * BATCH + b) * PROJ + h * PH;
            p0 = src[t];
            p1 = src[t + 128];
            if (t < PH - 256) p2 = src[t + 256];
        }

        const float* in = buf[ls & 1];
        const float* hb = h_sh[ls & 1];

        float h0 = hb[lane];
        float h1 = hb[lane + 32];
        float mx = warp_max_f32(fmaxf(h0, h1));
        float e0 = __expf(h0 - mx);
        float e1 = __expf(h1 - mx);
        e_sh[w][lane]      = e0;
        e_sh[w][lane + 32] = e1;
        float sm = e0 + e1;
        #pragma unroll
        for (int o = 16; o; o >>= 1) sm += __shfl_xor_sync(0xffffffffu, sm, o);
        float invTot = __fdividef(1.0f, sm);
        __syncwarp();

        ull k2[16];
        ld16p(k2, in + 64 + cofs);
        float vold = dot16p(W2, k2);
        vold += __shfl_xor_sync(0xffffffffu, vold, 1);
        float coef = in[320] * (in[128 + i] - vold);
        ull cd = pack_dup(coef);
        #pragma unroll
        for (int j = 0; j < 16; j++) W2[j] = fma_f32x2(cd, k2[j], W2[j]);

        ull q2[16];
        ld16p(q2, in + cofs);
        float z = dot16p(W2, q2);
        z += __shfl_xor_sync(0xffffffffu, z, 1);

        ull rk2[16];
        ld16p(rk2, in + 192 + cofs);
        float voldR = dot16p(R2, rk2);
        voldR += __shfl_xor_sync(0xffffffffu, voldR, 1);
        float coefR = in[321] * (in[256 + i] - voldR);
        ull crd = pack_dup(coefR);
        #pragma unroll
        for (int j = 0; j < 16; j++) R2[j] = fma_f32x2(crd, rk2[j], R2[j]);

        ull er2[16];
        ld16p(er2, &e_sh[w][cofs]);
        float hd = dot16p(R2, er2);
        hd += __shfl_xor_sync(0xffffffffu, hd, 1);
        float hn = z + hd * invTot;

        if (c == 0) {
            h_sh[(ls + 1) & 1][i] = hn;
            __nv_bfloat16 hi, lo;
            split_bf16(hn, hi, lo);
            size_t idx = (size_t)(s * BATCH + b) * OUTD + h * DHEAD + i;
            g_hs_hi[idx] = hi;
            g_hs_lo[idx] = lo;
        }
        __syncthreads();
    }

    // persist state (CS even -> final h sits in h_sh[0])
    {
        ull* ws = g_Wst + ((size_t)bh * 128 + t) * 16;
        ull* rs = g_Rst + ((size_t)bh * 128 + t) * 16;
        #pragma unroll
        for (int j = 0; j < 16; j++) { ws[j] = W2[j]; rs[j] = R2[j]; }
        if (t < 64) g_hst[bh * 64 + t] = h_sh[0][t];
    }
}

// ============================================================
// Launch: 2-stream chunked pipeline (graph-capturable fork/join)
// ============================================================
extern "C" void kernel_launch(void* const* d_in, const int* in_sizes, int n_in,
                              void* d_out, int out_size)
{
    const float* x      = (const float*)d_in[0];
    const float* W_slow = (const float*)d_in[1];
    const float* W_out  = (const float*)d_in[2];
    const float* gamma  = (const float*)d_in[3];
    const float* betap  = (const float*)d_in[4];
    float* out = (float*)d_out;

    float* p_qkvb = nullptr;
    __nv_bfloat16 *p_nh = nullptr, *p_nl = nullptr, *p_hh = nullptr, *p_hl = nullptr;
    __nv_bfloat16 *p_wsh = nullptr, *p_wsl = nullptr, *p_woh = nullptr, *p_wol = nullptr;
    cudaGetSymbolAddress((void**)&p_qkvb, g_qkvb);
    cudaGetSymbolAddress((void**)&p_nh,   g_normed_hi);
    cudaGetSymbolAddress((void**)&p_nl,   g_normed_lo);
    cudaGetSymbolAddress((void**)&p_hh,   g_hs_hi);
    cudaGetSymbolAddress((void**)&p_hl,   g_hs_lo);
    cudaGetSymbolAddress((void**)&p_wsh,  g_wslow_hi);
    cudaGetSymbolAddress((void**)&p_wsl,  g_wslow_lo);
    cudaGetSymbolAddress((void**)&p_woh,  g_wout_hi);
    cudaGetSymbolAddress((void**)&p_wol,  g_wout_lo);

    static bool init_done = false;
    static cudaStream_t sB;
    static cudaEvent_t evA[NCHUNK], evB[NCHUNK];
    if (!init_done) {
        cudaFuncSetAttribute((const void*)mma_gemm_nt<false>,
                             cudaFuncAttributeMaxDynamicSharedMemorySize,
                             GEMM_SMEM_BYTES);
        cudaFuncSetAttribute((const void*)mma_gemm_nt<true>,
                             cudaFuncAttributeMaxDynamicSharedMemorySize,
                             GEMM_SMEM_BYTES);
        cudaStreamCreateWithFlags(&sB, cudaStreamNonBlocking);
        for (int cidx = 0; cidx < NCHUNK; cidx++) {
            cudaEventCreateWithFlags(&evA[cidx], cudaEventDisableTiming);
            cudaEventCreateWithFlags(&evB[cidx], cudaEventDisableTiming);
        }
        init_done = true;
    }

    // 0. weight splits + LayerNorm (default stream)
    {
        int n1 = PROJ * INDIM;
        split_kernel<<<(n1 / 8 + 255) / 256, 256>>>(W_slow, p_wsh, p_wsl, n1);
        int n2 = INDIM * OUTD;
        split_kernel<<<(n2 / 8 + 255) / 256, 256>>>(W_out, p_woh, p_wol, n2);
    }
    ln_kernel<<<MROWS, 256>>>(x, gamma, betap);

    // 1. GEMM1 + act in chunks (default stream), signal evA[c]
    for (int cidx = 0; cidx < NCHUNK; cidx++) {
        dim3 grid((PROJ + TC_BN - 1) / TC_BN, MCHUNK / TC_BM);
        mma_gemm_nt<false><<<grid, 256, GEMM_SMEM_BYTES>>>(
            p_nh, p_nl, p_wsh, p_wsl, p_qkvb, nullptr, PROJ, INDIM,
            cidx * MCHUNK);
        act_kernel<<<MCHUNK, 256>>>(cidx * MCHUNK);
        cudaEventRecord(evA[cidx], 0);
    }

    // 2. scan chunks on stream B (each waits its input chunk)
    for (int cidx = 0; cidx < NCHUNK; cidx++) {
        cudaStreamWaitEvent(sB, evA[cidx], 0);
        scan_kernel<<<BATCH * HEADS, 128, 0, sB>>>(cidx * CS, cidx == 0 ? 1 : 0);
        cudaEventRecord(evB[cidx], sB);
    }

    // 3. GEMM2 chunks on default stream, each gated on its scan chunk
    for (int cidx = 0; cidx < NCHUNK; cidx++) {
        cudaStreamWaitEvent(0, evB[cidx], 0);
        dim3 grid(INDIM / TC_BN, MCHUNK / TC_BM);
        mma_gemm_nt<true><<<grid, 256, GEMM_SMEM_BYTES>>>(
            p_hh, p_hl, p_woh, p_wol, out, x, INDIM, OUTD,
            cidx * MCHUNK);
    }
}